// round 1
// baseline (speedup 1.0000x reference)
#include <cuda_runtime.h>
#include <math.h>

// Problem constants
#define B_   64
#define A_   8
#define S_   512          // B_*A_ slices
#define F_   256          // DIM (in channels)
#define T_   256          // time dim
#define HID  512          // heads*c
#define OC3  1536         // 3*HID
#define HEADS 4
#define C_   128

// Scratch (static __device__ globals — no runtime allocation)
__device__ float g_temb[(size_t)S_ * OC3];                       // 3 MB
__device__ float g_qkv [(size_t)S_ * OC3 * T_];                  // 805 MB
__device__ float g_ctx [(size_t)S_ * HEADS * C_ * C_];           // 134 MB
__device__ float g_att [(size_t)B_ * HID * A_ * T_];             // 268 MB

// ---------------------------------------------------------------------------
// Kernel 1: temb[s, o] = mish(time[s,:]) @ w_time[o,:] + b_time[o]
// one block per slice s; mish vector in smem; warp-per-output dot products
// ---------------------------------------------------------------------------
__global__ void k_temb(const float* __restrict__ time_in,
                       const float* __restrict__ w_time,
                       const float* __restrict__ b_time) {
    int s = blockIdx.x;
    int t = threadIdx.x;
    __shared__ float m[256];
    float v = time_in[(size_t)s * 256 + t];
    float sp = (v > 20.f) ? v : log1pf(__expf(v));
    m[t] = v * tanhf(sp);
    __syncthreads();

    int warp = t >> 5, lane = t & 31;
    for (int o = warp; o < OC3; o += 8) {
        const float* w = w_time + (size_t)o * 256;
        float acc = 0.f;
        #pragma unroll 4
        for (int e = lane; e < 256; e += 32) acc += m[e] * w[e];
        #pragma unroll
        for (int off = 16; off; off >>= 1) acc += __shfl_down_sync(0xffffffffu, acc, off);
        if (lane == 0) g_temb[(size_t)s * OC3 + o] = acc + b_time[o];
    }
}

// ---------------------------------------------------------------------------
// Kernel 2: qkv[s, o, t] = sum_f w_qkv[o,f] * x[s, f, t] + temb[s, o]
// M=1536, N=256, K=256; 64x64 tile, 4x4/thread, K-tile 16
// ---------------------------------------------------------------------------
__global__ void k_qkv(const float* __restrict__ W, const float* __restrict__ X) {
    __shared__ float As[16][65];
    __shared__ float Bs[16][64];
    int s  = blockIdx.z;
    int m0 = blockIdx.y * 64;
    int n0 = blockIdx.x * 64;
    int tid = threadIdx.x;
    int tx = tid & 15, ty = tid >> 4;

    const float* Xs = X + (size_t)s * F_ * T_;
    float acc[4][4] = {};

    int a_row = tid >> 2;          // 0..63  (m)
    int a_col = (tid & 3) * 4;     // 0..12  (k)
    int b_row = tid >> 4;          // 0..15  (k)
    int b_col = (tid & 15) * 4;    // 0..60  (n)

    for (int k0 = 0; k0 < F_; k0 += 16) {
        float4 av = *(const float4*)(W + (size_t)(m0 + a_row) * F_ + k0 + a_col);
        As[a_col + 0][a_row] = av.x;
        As[a_col + 1][a_row] = av.y;
        As[a_col + 2][a_row] = av.z;
        As[a_col + 3][a_row] = av.w;
        *(float4*)&Bs[b_row][b_col] =
            *(const float4*)(Xs + (size_t)(k0 + b_row) * T_ + n0 + b_col);
        __syncthreads();
        #pragma unroll
        for (int kk = 0; kk < 16; kk++) {
            float a[4], b[4];
            #pragma unroll
            for (int i = 0; i < 4; i++) a[i] = As[kk][ty * 4 + i];
            #pragma unroll
            for (int j = 0; j < 4; j++) b[j] = Bs[kk][tx * 4 + j];
            #pragma unroll
            for (int i = 0; i < 4; i++)
                #pragma unroll
                for (int j = 0; j < 4; j++) acc[i][j] += a[i] * b[j];
        }
        __syncthreads();
    }

    float* Co = g_qkv + (size_t)s * OC3 * T_;
    #pragma unroll
    for (int i = 0; i < 4; i++) {
        int m = m0 + ty * 4 + i;
        float tadd = g_temb[(size_t)s * OC3 + m];
        float4 v;
        v.x = acc[i][0] + tadd; v.y = acc[i][1] + tadd;
        v.z = acc[i][2] + tadd; v.w = acc[i][3] + tadd;
        *(float4*)(Co + (size_t)m * T_ + n0 + tx * 4) = v;
    }
}

// ---------------------------------------------------------------------------
// Kernel 3: softmax over t for k-part rows (o in [512,1024))
// one block per (s, row) ; 256 threads, 1 element each
// ---------------------------------------------------------------------------
__global__ void k_softmax() {
    int r = blockIdx.x;       // 0..511 (h*128+d)
    int s = blockIdx.y;       // slice
    float* p = g_qkv + (size_t)s * OC3 * T_ + (size_t)(HID + r) * T_;
    int t = threadIdx.x;
    __shared__ float red[256];
    float v = p[t];
    red[t] = v; __syncthreads();
    #pragma unroll
    for (int off = 128; off > 0; off >>= 1) {
        if (t < off) red[t] = fmaxf(red[t], red[t + off]);
        __syncthreads();
    }
    float mx = red[0]; __syncthreads();
    float e = __expf(v - mx);
    red[t] = e; __syncthreads();
    #pragma unroll
    for (int off = 128; off > 0; off >>= 1) {
        if (t < off) red[t] += red[t + off];
        __syncthreads();
    }
    p[t] = e * (1.f / red[0]);
}

// ---------------------------------------------------------------------------
// Kernel 4: context[sb, d, e] = sum_t ksm[d,t] * v[e,t]   (NT GEMM 128x128x256)
// ---------------------------------------------------------------------------
__global__ void k_ctx() {
    __shared__ float As[16][65];
    __shared__ float Bs[16][65];
    int sb = blockIdx.z;
    int s = sb >> 2, h = sb & 3;
    const float* Ab = g_qkv + (size_t)s * OC3 * T_ + (size_t)(HID + h * C_) * T_;       // ksm
    const float* Bb = g_qkv + (size_t)s * OC3 * T_ + (size_t)(2 * HID + h * C_) * T_;   // v
    int m0 = blockIdx.y * 64;
    int n0 = blockIdx.x * 64;
    int tid = threadIdx.x;
    int tx = tid & 15, ty = tid >> 4;
    float acc[4][4] = {};

    int a_row = tid >> 2;
    int a_col = (tid & 3) * 4;

    for (int k0 = 0; k0 < T_; k0 += 16) {
        float4 av = *(const float4*)(Ab + (size_t)(m0 + a_row) * T_ + k0 + a_col);
        As[a_col + 0][a_row] = av.x;
        As[a_col + 1][a_row] = av.y;
        As[a_col + 2][a_row] = av.z;
        As[a_col + 3][a_row] = av.w;
        float4 bv = *(const float4*)(Bb + (size_t)(n0 + a_row) * T_ + k0 + a_col);
        Bs[a_col + 0][a_row] = bv.x;
        Bs[a_col + 1][a_row] = bv.y;
        Bs[a_col + 2][a_row] = bv.z;
        Bs[a_col + 3][a_row] = bv.w;
        __syncthreads();
        #pragma unroll
        for (int kk = 0; kk < 16; kk++) {
            float a[4], b[4];
            #pragma unroll
            for (int i = 0; i < 4; i++) a[i] = As[kk][ty * 4 + i];
            #pragma unroll
            for (int j = 0; j < 4; j++) b[j] = Bs[kk][tx * 4 + j];
            #pragma unroll
            for (int i = 0; i < 4; i++)
                #pragma unroll
                for (int j = 0; j < 4; j++) acc[i][j] += a[i] * b[j];
        }
        __syncthreads();
    }

    float* Co = g_ctx + (size_t)sb * C_ * C_;
    #pragma unroll
    for (int i = 0; i < 4; i++) {
        int m = m0 + ty * 4 + i;
        *(float4*)(Co + (size_t)m * C_ + n0 + tx * 4) =
            make_float4(acc[i][0], acc[i][1], acc[i][2], acc[i][3]);
    }
}

// ---------------------------------------------------------------------------
// Kernel 5: out[sb, e, t] = sum_d ctx[d,e] * q[d,t]  (TN GEMM 128x256x128)
// write into g_att laid out [b, hid, a, t]
// ---------------------------------------------------------------------------
__global__ void k_apply() {
    __shared__ float As[16][64];
    __shared__ float Bs[16][64];
    int sb = blockIdx.z;
    int s = sb >> 2, h = sb & 3;
    int b = s >> 3, a = s & 7;
    const float* Ab = g_ctx + (size_t)sb * C_ * C_;                       // [d, e]
    const float* Bb = g_qkv + (size_t)s * OC3 * T_ + (size_t)(h * C_) * T_; // q [d, t]
    int m0 = blockIdx.y * 64;   // e
    int n0 = blockIdx.x * 64;   // t
    int tid = threadIdx.x;
    int tx = tid & 15, ty = tid >> 4;
    float acc[4][4] = {};

    int r16 = tid >> 4;            // 0..15 (k)
    int c4  = (tid & 15) * 4;      // 0..60

    for (int k0 = 0; k0 < C_; k0 += 16) {
        *(float4*)&As[r16][c4] = *(const float4*)(Ab + (size_t)(k0 + r16) * C_ + m0 + c4);
        *(float4*)&Bs[r16][c4] = *(const float4*)(Bb + (size_t)(k0 + r16) * T_ + n0 + c4);
        __syncthreads();
        #pragma unroll
        for (int kk = 0; kk < 16; kk++) {
            float av[4], bv[4];
            #pragma unroll
            for (int i = 0; i < 4; i++) av[i] = As[kk][ty * 4 + i];
            #pragma unroll
            for (int j = 0; j < 4; j++) bv[j] = Bs[kk][tx * 4 + j];
            #pragma unroll
            for (int i = 0; i < 4; i++)
                #pragma unroll
                for (int j = 0; j < 4; j++) acc[i][j] += av[i] * bv[j];
        }
        __syncthreads();
    }

    #pragma unroll
    for (int i = 0; i < 4; i++) {
        int f = h * C_ + m0 + ty * 4 + i;
        size_t base = ((size_t)b * HID + f) * (A_ * T_) + (size_t)a * T_;
        *(float4*)(g_att + base + n0 + tx * 4) =
            make_float4(acc[i][0], acc[i][1], acc[i][2], acc[i][3]);
    }
}

// ---------------------------------------------------------------------------
// Kernel 6: y[s, o, t] = sum_f w_out[o,f] * att[b, f, a, t] + b_out[o]
// M=256, N=256, K=512
// ---------------------------------------------------------------------------
__global__ void k_out(const float* __restrict__ W, const float* __restrict__ bias,
                      float* __restrict__ out) {
    __shared__ float As[16][65];
    __shared__ float Bs[16][64];
    int s = blockIdx.z;
    int b = s >> 3, a = s & 7;
    const float* Bb = g_att + (size_t)b * HID * A_ * T_ + (size_t)a * T_;
    int m0 = blockIdx.y * 64;
    int n0 = blockIdx.x * 64;
    int tid = threadIdx.x;
    int tx = tid & 15, ty = tid >> 4;
    float acc[4][4] = {};

    int a_row = tid >> 2;
    int a_col = (tid & 3) * 4;
    int b_row = tid >> 4;
    int b_col = (tid & 15) * 4;

    for (int k0 = 0; k0 < HID; k0 += 16) {
        float4 av = *(const float4*)(W + (size_t)(m0 + a_row) * HID + k0 + a_col);
        As[a_col + 0][a_row] = av.x;
        As[a_col + 1][a_row] = av.y;
        As[a_col + 2][a_row] = av.z;
        As[a_col + 3][a_row] = av.w;
        *(float4*)&Bs[b_row][b_col] =
            *(const float4*)(Bb + (size_t)(k0 + b_row) * (A_ * T_) + n0 + b_col);
        __syncthreads();
        #pragma unroll
        for (int kk = 0; kk < 16; kk++) {
            float av2[4], bv2[4];
            #pragma unroll
            for (int i = 0; i < 4; i++) av2[i] = As[kk][ty * 4 + i];
            #pragma unroll
            for (int j = 0; j < 4; j++) bv2[j] = Bs[kk][tx * 4 + j];
            #pragma unroll
            for (int i = 0; i < 4; i++)
                #pragma unroll
                for (int j = 0; j < 4; j++) acc[i][j] += av2[i] * bv2[j];
        }
        __syncthreads();
    }

    #pragma unroll
    for (int i = 0; i < 4; i++) {
        int m = m0 + ty * 4 + i;
        float bo = bias[m];
        *(float4*)(out + ((size_t)s * 256 + m) * T_ + n0 + tx * 4) =
            make_float4(acc[i][0] + bo, acc[i][1] + bo, acc[i][2] + bo, acc[i][3] + bo);
    }
}

// ---------------------------------------------------------------------------
extern "C" void kernel_launch(void* const* d_in, const int* in_sizes, int n_in,
                              void* d_out, int out_size) {
    (void)in_sizes; (void)n_in; (void)out_size;
    const float* x       = (const float*)d_in[0];
    const float* time_in = (const float*)d_in[1];
    const float* w_qkv   = (const float*)d_in[2];
    const float* w_time  = (const float*)d_in[3];
    const float* b_time  = (const float*)d_in[4];
    const float* w_out   = (const float*)d_in[5];
    const float* b_out   = (const float*)d_in[6];
    float* out = (float*)d_out;

    k_temb<<<S_, 256>>>(time_in, w_time, b_time);
    k_qkv<<<dim3(T_ / 64, OC3 / 64, S_), 256>>>(w_qkv, x);
    k_softmax<<<dim3(HID, S_), 256>>>();
    k_ctx<<<dim3(C_ / 64, C_ / 64, S_ * HEADS), 256>>>();
    k_apply<<<dim3(T_ / 64, C_ / 64, S_ * HEADS), 256>>>();
    k_out<<<dim3(T_ / 64, 256 / 64, S_), 256>>>(w_out, b_out, out);
}

// round 2
// speedup vs baseline: 1.3885x; 1.3885x over previous
#include <cuda_runtime.h>
#include <math.h>

// Problem constants
#define B_   64
#define A_   8
#define S_   512          // B_*A_ slices
#define F_   256          // DIM (in channels)
#define T_   256          // time dim
#define HID  512          // heads*c
#define OC3  1536         // 3*HID
#define HEADS 4
#define C_   128

#define BM 128
#define BN 128
#define BK 8
#define LDS_ 132          // padded smem row stride (floats)

// Scratch (static __device__ globals — no runtime allocation)
__device__ float g_temb[(size_t)S_ * OC3];
__device__ float g_qkv [(size_t)S_ * OC3 * T_];
__device__ float g_ctx [(size_t)S_ * HEADS * C_ * C_];
__device__ float g_att [(size_t)B_ * HID * A_ * T_];

struct SmemBuf {
    float As[2][BK][LDS_];
    float Bs[2][BK][LDS_];
};

// ---------------------------------------------------------------------------
// Generic 128x128 block, 8x8/thread, K-tile 8, double-buffered GEMM body.
// AT: A global is [M,K] row-major (needs transpose on load into As[k][m])
//     else A global is [K,M] (direct).
// BT: B global is [N,K] row-major (transpose into Bs[k][n]) else [K,N] direct.
// ---------------------------------------------------------------------------
template<bool AT, bool BT>
__device__ __forceinline__ void gemm_tile(const float* __restrict__ Ab, int lda,
                                          const float* __restrict__ Bb, int ldb,
                                          int K, float acc[8][8], SmemBuf& sb)
{
    const int tid = threadIdx.x;
    const int tx = tid & 15, ty = tid >> 4;

    const int tr_row = tid >> 1;          // 0..127  (m or n), trans loads
    const int tr_kc  = (tid & 1) * 4;     // 0 or 4  (k),       trans loads
    const int dr_k   = tid >> 5;          // 0..7    (k),       direct loads
    const int dr_c   = (tid & 31) * 4;    // 0..124  (m/n),     direct loads

    // ---- load tile 0 into buffer 0 ----
    {
        if (AT) {
            float4 v = *(const float4*)(Ab + (size_t)tr_row * lda + tr_kc);
            sb.As[0][tr_kc + 0][tr_row] = v.x;
            sb.As[0][tr_kc + 1][tr_row] = v.y;
            sb.As[0][tr_kc + 2][tr_row] = v.z;
            sb.As[0][tr_kc + 3][tr_row] = v.w;
        } else {
            *(float4*)&sb.As[0][dr_k][dr_c] =
                *(const float4*)(Ab + (size_t)dr_k * lda + dr_c);
        }
        if (BT) {
            float4 v = *(const float4*)(Bb + (size_t)tr_row * ldb + tr_kc);
            sb.Bs[0][tr_kc + 0][tr_row] = v.x;
            sb.Bs[0][tr_kc + 1][tr_row] = v.y;
            sb.Bs[0][tr_kc + 2][tr_row] = v.z;
            sb.Bs[0][tr_kc + 3][tr_row] = v.w;
        } else {
            *(float4*)&sb.Bs[0][dr_k][dr_c] =
                *(const float4*)(Bb + (size_t)dr_k * ldb + dr_c);
        }
    }
    __syncthreads();

    const int nk = K / BK;
    for (int t = 0; t < nk; t++) {
        const int cur = t & 1;
        const int nxt = cur ^ 1;

        float4 va, vb;
        const bool more = (t + 1 < nk);
        if (more) {
            const int k0 = (t + 1) * BK;
            va = AT ? *(const float4*)(Ab + (size_t)tr_row * lda + k0 + tr_kc)
                    : *(const float4*)(Ab + (size_t)(k0 + dr_k) * lda + dr_c);
            vb = BT ? *(const float4*)(Bb + (size_t)tr_row * ldb + k0 + tr_kc)
                    : *(const float4*)(Bb + (size_t)(k0 + dr_k) * ldb + dr_c);
        }

        #pragma unroll
        for (int k = 0; k < BK; k++) {
            float a[8], b[8];
            *(float4*)&a[0] = *(float4*)&sb.As[cur][k][ty * 8];
            *(float4*)&a[4] = *(float4*)&sb.As[cur][k][ty * 8 + 4];
            *(float4*)&b[0] = *(float4*)&sb.Bs[cur][k][tx * 8];
            *(float4*)&b[4] = *(float4*)&sb.Bs[cur][k][tx * 8 + 4];
            #pragma unroll
            for (int i = 0; i < 8; i++)
                #pragma unroll
                for (int j = 0; j < 8; j++)
                    acc[i][j] += a[i] * b[j];
        }

        if (more) {
            if (AT) {
                sb.As[nxt][tr_kc + 0][tr_row] = va.x;
                sb.As[nxt][tr_kc + 1][tr_row] = va.y;
                sb.As[nxt][tr_kc + 2][tr_row] = va.z;
                sb.As[nxt][tr_kc + 3][tr_row] = va.w;
            } else {
                *(float4*)&sb.As[nxt][dr_k][dr_c] = va;
            }
            if (BT) {
                sb.Bs[nxt][tr_kc + 0][tr_row] = vb.x;
                sb.Bs[nxt][tr_kc + 1][tr_row] = vb.y;
                sb.Bs[nxt][tr_kc + 2][tr_row] = vb.z;
                sb.Bs[nxt][tr_kc + 3][tr_row] = vb.w;
            } else {
                *(float4*)&sb.Bs[nxt][dr_k][dr_c] = vb;
            }
            __syncthreads();
        }
    }
}

// ---------------------------------------------------------------------------
// Kernel 1: temb[s, o] = mish(time[s,:]) @ w_time[o,:] + b_time[o]
// ---------------------------------------------------------------------------
__global__ void k_temb(const float* __restrict__ time_in,
                       const float* __restrict__ w_time,
                       const float* __restrict__ b_time) {
    int s = blockIdx.x;
    int t = threadIdx.x;
    __shared__ float m[256];
    float v = time_in[(size_t)s * 256 + t];
    float sp = (v > 20.f) ? v : log1pf(__expf(v));
    m[t] = v * tanhf(sp);
    __syncthreads();

    int warp = t >> 5, lane = t & 31;
    for (int o = warp; o < OC3; o += 8) {
        const float* w = w_time + (size_t)o * 256;
        float acc = 0.f;
        #pragma unroll 4
        for (int e = lane; e < 256; e += 32) acc += m[e] * w[e];
        #pragma unroll
        for (int off = 16; off; off >>= 1) acc += __shfl_down_sync(0xffffffffu, acc, off);
        if (lane == 0) g_temb[(size_t)s * OC3 + o] = acc + b_time[o];
    }
}

// ---------------------------------------------------------------------------
// Kernel 2: qkv[s, o, t] = w_qkv[o,:] . x[s, :, t] + temb[s, o]
// ---------------------------------------------------------------------------
__global__ __launch_bounds__(256, 2)
void k_qkv2(const float* __restrict__ W, const float* __restrict__ X) {
    __shared__ SmemBuf sb;
    int s  = blockIdx.z;
    int m0 = blockIdx.y * BM;
    int n0 = blockIdx.x * BN;
    float acc[8][8] = {};
    gemm_tile<true, false>(W + (size_t)m0 * F_, F_,
                           X + (size_t)s * F_ * T_ + n0, T_, F_, acc, sb);

    int tid = threadIdx.x, tx = tid & 15, ty = tid >> 4;
    const float* te = g_temb + (size_t)s * OC3 + m0;
    float* Co = g_qkv + (size_t)s * OC3 * T_;
    #pragma unroll
    for (int i = 0; i < 8; i++) {
        int m = ty * 8 + i;
        float tadd = te[m];
        float* row = Co + (size_t)(m0 + m) * T_ + n0 + tx * 8;
        *(float4*)row = make_float4(acc[i][0] + tadd, acc[i][1] + tadd,
                                    acc[i][2] + tadd, acc[i][3] + tadd);
        *(float4*)(row + 4) = make_float4(acc[i][4] + tadd, acc[i][5] + tadd,
                                          acc[i][6] + tadd, acc[i][7] + tadd);
    }
}

// ---------------------------------------------------------------------------
// Kernel 3: softmax over t — one warp per row, 8 elems/lane, no block syncs
// ---------------------------------------------------------------------------
__global__ void k_softmax2() {
    int row  = blockIdx.x * 8 + (threadIdx.x >> 5);  // 0 .. S_*HID-1
    int lane = threadIdx.x & 31;
    int s = row >> 9;          // /512
    int r = row & 511;
    float* p = g_qkv + (size_t)s * OC3 * T_ + (size_t)(HID + r) * T_ + lane * 8;

    float4 v0 = *(float4*)p;
    float4 v1 = *(float4*)(p + 4);
    float mx = fmaxf(fmaxf(fmaxf(v0.x, v0.y), fmaxf(v0.z, v0.w)),
                     fmaxf(fmaxf(v1.x, v1.y), fmaxf(v1.z, v1.w)));
    #pragma unroll
    for (int off = 16; off; off >>= 1)
        mx = fmaxf(mx, __shfl_xor_sync(0xffffffffu, mx, off));

    v0.x = __expf(v0.x - mx); v0.y = __expf(v0.y - mx);
    v0.z = __expf(v0.z - mx); v0.w = __expf(v0.w - mx);
    v1.x = __expf(v1.x - mx); v1.y = __expf(v1.y - mx);
    v1.z = __expf(v1.z - mx); v1.w = __expf(v1.w - mx);

    float sm = v0.x + v0.y + v0.z + v0.w + v1.x + v1.y + v1.z + v1.w;
    #pragma unroll
    for (int off = 16; off; off >>= 1)
        sm += __shfl_xor_sync(0xffffffffu, sm, off);

    float inv = 1.f / sm;
    v0.x *= inv; v0.y *= inv; v0.z *= inv; v0.w *= inv;
    v1.x *= inv; v1.y *= inv; v1.z *= inv; v1.w *= inv;
    *(float4*)p = v0;
    *(float4*)(p + 4) = v1;
}

// ---------------------------------------------------------------------------
// Kernel 4: context[sb, d, e] = sum_t ksm[d,t] * v[e,t]   (NT, 128x128x256)
// ---------------------------------------------------------------------------
__global__ __launch_bounds__(256, 2)
void k_ctx2() {
    __shared__ SmemBuf sb_;
    int sb = blockIdx.z;
    int s = sb >> 2, h = sb & 3;
    const float* Ab = g_qkv + (size_t)s * OC3 * T_ + (size_t)(HID + h * C_) * T_;
    const float* Bb = g_qkv + (size_t)s * OC3 * T_ + (size_t)(2 * HID + h * C_) * T_;
    float acc[8][8] = {};
    gemm_tile<true, true>(Ab, T_, Bb, T_, T_, acc, sb_);

    int tid = threadIdx.x, tx = tid & 15, ty = tid >> 4;
    float* Co = g_ctx + (size_t)sb * C_ * C_;
    #pragma unroll
    for (int i = 0; i < 8; i++) {
        float* row = Co + (size_t)(ty * 8 + i) * C_ + tx * 8;
        *(float4*)row = make_float4(acc[i][0], acc[i][1], acc[i][2], acc[i][3]);
        *(float4*)(row + 4) = make_float4(acc[i][4], acc[i][5], acc[i][6], acc[i][7]);
    }
}

// ---------------------------------------------------------------------------
// Kernel 5: out[sb, e, t] = sum_d ctx[d,e] * q[d,t]  (TN, 128x256x128)
// ---------------------------------------------------------------------------
__global__ __launch_bounds__(256, 2)
void k_apply2() {
    __shared__ SmemBuf sb_;
    int sb = blockIdx.z;
    int s = sb >> 2, h = sb & 3;
    int b = s >> 3, a = s & 7;
    int n0 = blockIdx.x * BN;
    const float* Ab = g_ctx + (size_t)sb * C_ * C_;                          // [d, e]
    const float* Bb = g_qkv + (size_t)s * OC3 * T_ + (size_t)(h * C_) * T_ + n0;
    float acc[8][8] = {};
    gemm_tile<false, false>(Ab, C_, Bb, T_, C_, acc, sb_);

    int tid = threadIdx.x, tx = tid & 15, ty = tid >> 4;
    #pragma unroll
    for (int i = 0; i < 8; i++) {
        int f = h * C_ + ty * 8 + i;
        float* row = g_att + ((size_t)b * HID + f) * (A_ * T_) + (size_t)a * T_
                     + n0 + tx * 8;
        *(float4*)row = make_float4(acc[i][0], acc[i][1], acc[i][2], acc[i][3]);
        *(float4*)(row + 4) = make_float4(acc[i][4], acc[i][5], acc[i][6], acc[i][7]);
    }
}

// ---------------------------------------------------------------------------
// Kernel 6: y[s, o, t] = w_out[o,:] . att[b, :, a, t] + b_out[o]
// ---------------------------------------------------------------------------
__global__ __launch_bounds__(256, 2)
void k_out2(const float* __restrict__ W, const float* __restrict__ bias,
            float* __restrict__ out) {
    __shared__ SmemBuf sb_;
    int s = blockIdx.z;
    int b = s >> 3, a = s & 7;
    int m0 = blockIdx.y * BM;
    int n0 = blockIdx.x * BN;
    const float* Bb = g_att + (size_t)b * HID * A_ * T_ + (size_t)a * T_ + n0;
    float acc[8][8] = {};
    gemm_tile<true, false>(W + (size_t)m0 * HID, HID, Bb, A_ * T_, HID, acc, sb_);

    int tid = threadIdx.x, tx = tid & 15, ty = tid >> 4;
    #pragma unroll
    for (int i = 0; i < 8; i++) {
        int m = m0 + ty * 8 + i;
        float bo = bias[m];
        float* row = out + ((size_t)s * 256 + m) * T_ + n0 + tx * 8;
        *(float4*)row = make_float4(acc[i][0] + bo, acc[i][1] + bo,
                                    acc[i][2] + bo, acc[i][3] + bo);
        *(float4*)(row + 4) = make_float4(acc[i][4] + bo, acc[i][5] + bo,
                                          acc[i][6] + bo, acc[i][7] + bo);
    }
}

// ---------------------------------------------------------------------------
extern "C" void kernel_launch(void* const* d_in, const int* in_sizes, int n_in,
                              void* d_out, int out_size) {
    (void)in_sizes; (void)n_in; (void)out_size;
    const float* x       = (const float*)d_in[0];
    const float* time_in = (const float*)d_in[1];
    const float* w_qkv   = (const float*)d_in[2];
    const float* w_time  = (const float*)d_in[3];
    const float* b_time  = (const float*)d_in[4];
    const float* w_out   = (const float*)d_in[5];
    const float* b_out   = (const float*)d_in[6];
    float* out = (float*)d_out;

    k_temb<<<S_, 256>>>(time_in, w_time, b_time);
    k_qkv2<<<dim3(T_ / BN, OC3 / BM, S_), 256>>>(w_qkv, x);
    k_softmax2<<<(S_ * HID) / 8, 256>>>();
    k_ctx2<<<dim3(1, 1, S_ * HEADS), 256>>>();
    k_apply2<<<dim3(T_ / BN, 1, S_ * HEADS), 256>>>();
    k_out2<<<dim3(T_ / BN, 256 / BM, S_), 256>>>(w_out, b_out, out);
}

// round 3
// speedup vs baseline: 2.0970x; 1.5103x over previous
#include <cuda_runtime.h>
#include <cuda_bf16.h>
#include <math.h>

// Problem constants
#define B_   64
#define A_   8
#define S_   512          // B_*A_ slices
#define F_   256          // DIM (in channels)
#define T_   256          // time dim
#define HID  512          // heads*c
#define OC3  1536         // 3*HID
#define HEADS 4
#define C_   128

#define BK 8
#define LDS_ 132

// ---------------------------------------------------------------------------
// Scratch (static __device__ globals — no runtime allocation)
// ---------------------------------------------------------------------------
__device__ float g_temb[(size_t)S_ * OC3];
__device__ float g_qkv [(size_t)S_ * OC3 * T_];                 // 805 MB
__device__ float g_ctx [(size_t)S_ * HEADS * C_ * C_];          // 134 MB
__device__ float g_att [(size_t)S_ * HID * T_];                 // 268 MB  [s][f][t]

// Fragment-packed bf16 hi/lo operand buffers
// A-pack: [band(128 rows)][kstep][mfrag(8)][plane(hi,lo)][lane] uint4
__device__ uint4 gA_qkv[(size_t)12 * 16 * 8 * 2 * 32];          // 1.5 MB
__device__ uint4 gA_out[(size_t)2 * 32 * 8 * 2 * 32];           // 0.5 MB
// B-pack: [slice][band(128 cols)][kstep][nfrag(16)][plane][lane] uint2
__device__ uint2 gB_x  [(size_t)S_ * 2 * 16 * 16 * 2 * 32];     // 134 MB
__device__ uint2 gB_att[(size_t)S_ * 2 * 32 * 16 * 2 * 32];     // 268 MB

#define BX_SLICE   ((size_t)2 * 16 * 16 * 2 * 32)   // uint2 per slice (x)
#define BATT_SLICE ((size_t)2 * 32 * 16 * 2 * 32)   // uint2 per slice (att)

// ---------------------------------------------------------------------------
// helpers
// ---------------------------------------------------------------------------
__device__ __forceinline__ unsigned bpack(float x, float y) {
    __nv_bfloat162 h = __floats2bfloat162_rn(x, y);
    return *reinterpret_cast<unsigned*>(&h);
}
__device__ __forceinline__ void bsplit(float v, float& hi, float& lo) {
    __nv_bfloat16 h = __float2bfloat16(v);
    hi = __bfloat162float(h);
    lo = v - hi;
}
__device__ __forceinline__ void mma_bf16(float* c, const uint4& a, const uint2& b) {
    asm volatile(
        "mma.sync.aligned.m16n8k16.row.col.f32.bf16.bf16.f32 "
        "{%0,%1,%2,%3}, {%4,%5,%6,%7}, {%8,%9}, {%0,%1,%2,%3};\n"
        : "+f"(c[0]), "+f"(c[1]), "+f"(c[2]), "+f"(c[3])
        : "r"(a.x), "r"(a.y), "r"(a.z), "r"(a.w), "r"(b.x), "r"(b.y));
}

// ---------------------------------------------------------------------------
// conv_A: fp32 [M x K] row-major -> fragment-packed bf16 hi/lo
// one warp per 16x16 fragment
// ---------------------------------------------------------------------------
__global__ void conv_A(const float* __restrict__ src, int lda, int Ksteps,
                       uint4* __restrict__ dst) {
    int wg   = blockIdx.x * 8 + (threadIdx.x >> 5);
    int lane = threadIdx.x & 31;
    int mf   = wg & 7;
    int ks   = (wg >> 3) % Ksteps;
    int band = wg / (8 * Ksteps);
    int g = lane >> 2, tc = (lane & 3) * 2;

    const float* p = src + (size_t)(band * 128 + mf * 16 + g) * lda + ks * 16 + tc;
    float2 p00 = *(const float2*)p;
    float2 p01 = *(const float2*)(p + 8);
    float2 p10 = *(const float2*)(p + (size_t)8 * lda);
    float2 p11 = *(const float2*)(p + (size_t)8 * lda + 8);

    float h00x,l00x,h00y,l00y, h10x,l10x,h10y,l10y;
    float h01x,l01x,h01y,l01y, h11x,l11x,h11y,l11y;
    bsplit(p00.x,h00x,l00x); bsplit(p00.y,h00y,l00y);
    bsplit(p10.x,h10x,l10x); bsplit(p10.y,h10y,l10y);
    bsplit(p01.x,h01x,l01x); bsplit(p01.y,h01y,l01y);
    bsplit(p11.x,h11x,l11x); bsplit(p11.y,h11y,l11y);

    uint4 hi, lo;
    hi.x = bpack(h00x,h00y); hi.y = bpack(h10x,h10y);
    hi.z = bpack(h01x,h01y); hi.w = bpack(h11x,h11y);
    lo.x = bpack(l00x,l00y); lo.y = bpack(l10x,l10y);
    lo.z = bpack(l01x,l01y); lo.w = bpack(l11x,l11y);

    size_t base = ((((size_t)band * Ksteps + ks) * 8 + mf) * 2) * 32 + lane;
    dst[base]      = hi;
    dst[base + 32] = lo;
}

// ---------------------------------------------------------------------------
// conv_Bd: fp32 [K x N] row-major (per-slice) -> fragment-packed bf16 hi/lo
// one warp per 16x8 fragment
// ---------------------------------------------------------------------------
__global__ void conv_Bd(const float* __restrict__ srcbase, int ldb, int Ksteps,
                        size_t src_slice_stride,
                        uint2* __restrict__ dstbase, size_t dst_slice_stride) {
    int s = blockIdx.y;
    const float* src = srcbase + (size_t)s * src_slice_stride;
    uint2* dst = dstbase + (size_t)s * dst_slice_stride;

    int wg   = blockIdx.x * 8 + (threadIdx.x >> 5);
    int lane = threadIdx.x & 31;
    int nf   = wg & 15;
    int ks   = (wg >> 4) % Ksteps;
    int band = wg / (16 * Ksteps);
    int g = lane >> 2, tc = (lane & 3) * 2;

    int n = band * 128 + nf * 8 + g;
    const float* p = src + (size_t)(ks * 16 + tc) * ldb + n;
    float v0 = p[0];
    float v1 = p[(size_t)ldb];
    float v2 = p[(size_t)8 * ldb];
    float v3 = p[(size_t)9 * ldb];

    float h0,l0,h1,l1,h2,l2,h3,l3;
    bsplit(v0,h0,l0); bsplit(v1,h1,l1); bsplit(v2,h2,l2); bsplit(v3,h3,l3);

    size_t base = ((((size_t)band * Ksteps + ks) * 16 + nf) * 2) * 32 + lane;
    dst[base]      = make_uint2(bpack(h0,h1), bpack(h2,h3));
    dst[base + 32] = make_uint2(bpack(l0,l1), bpack(l2,l3));
}

// ---------------------------------------------------------------------------
// mma tile core: 128x128 CTA tile, 8 warps (2x4), warp tile 64x32,
// 3-pass bf16 split accumulate, double-buffered smem.
// Achunks/Bchunks point at the (band, kstep=0) 8KB chunk; consecutive
// ksteps are +512 uint4.
// ---------------------------------------------------------------------------
__device__ __forceinline__ void mma_tile(const uint4* __restrict__ Achunks,
                                         const uint4* __restrict__ Bchunks,
                                         int Ksteps, float acc[4][4][4]) {
    __shared__ uint4 sA[2][512];
    __shared__ uint4 sB[2][512];

    int tid = threadIdx.x;
    int wid = tid >> 5, lane = tid & 31;
    int wm = wid >> 2, wn = wid & 3;

    sA[0][tid] = Achunks[tid]; sA[0][tid + 256] = Achunks[tid + 256];
    sB[0][tid] = Bchunks[tid]; sB[0][tid + 256] = Bchunks[tid + 256];
    __syncthreads();

    for (int ks = 0; ks < Ksteps; ks++) {
        int cur = ks & 1, nxt = cur ^ 1;
        uint4 na0, na1, nb0, nb1;
        bool more = (ks + 1 < Ksteps);
        if (more) {
            const uint4* An = Achunks + (size_t)(ks + 1) * 512;
            const uint4* Bn = Bchunks + (size_t)(ks + 1) * 512;
            na0 = An[tid]; na1 = An[tid + 256];
            nb0 = Bn[tid]; nb1 = Bn[tid + 256];
        }

        uint4 a[4][2];
        uint2 b[4][2];
        const uint4* sa  = &sA[cur][0];
        const uint2* sbp = (const uint2*)&sB[cur][0];
        #pragma unroll
        for (int i = 0; i < 4; i++) {
            int mf = wm * 4 + i;
            a[i][0] = sa[(mf * 2 + 0) * 32 + lane];
            a[i][1] = sa[(mf * 2 + 1) * 32 + lane];
        }
        #pragma unroll
        for (int j = 0; j < 4; j++) {
            int nf = wn * 4 + j;
            b[j][0] = sbp[(nf * 2 + 0) * 32 + lane];
            b[j][1] = sbp[(nf * 2 + 1) * 32 + lane];
        }
        #pragma unroll
        for (int i = 0; i < 4; i++)
            #pragma unroll
            for (int j = 0; j < 4; j++) {
                mma_bf16(acc[i][j], a[i][0], b[j][0]);   // hi*hi
                mma_bf16(acc[i][j], a[i][0], b[j][1]);   // hi*lo
                mma_bf16(acc[i][j], a[i][1], b[j][0]);   // lo*hi
            }

        if (more) {
            sA[nxt][tid] = na0; sA[nxt][tid + 256] = na1;
            sB[nxt][tid] = nb0; sB[nxt][tid + 256] = nb1;
            __syncthreads();
        }
    }
}

// ---------------------------------------------------------------------------
// qkv GEMM (mma): g_qkv[s,o,t] = w_qkv[o,:].x[s,:,t] + temb[s,o]
// ---------------------------------------------------------------------------
__global__ __launch_bounds__(256, 1)
void k_qkv_mma(const uint4* __restrict__ Ap, const uint2* __restrict__ Bp) {
    int s = blockIdx.z, bandA = blockIdx.y, bandB = blockIdx.x;
    const uint4* Ach = Ap + (size_t)bandA * 16 * 512;
    const uint4* Bch = (const uint4*)(Bp + (size_t)s * BX_SLICE) + (size_t)bandB * 16 * 512;

    float acc[4][4][4] = {};
    mma_tile(Ach, Bch, 16, acc);

    int tid = threadIdx.x, wid = tid >> 5, lane = tid & 31;
    int wm = wid >> 2, wn = wid & 3;
    int g = lane >> 2, tc = (lane & 3) * 2;
    float* Co = g_qkv + (size_t)s * OC3 * T_;
    const float* te = g_temb + (size_t)s * OC3;

    #pragma unroll
    for (int i = 0; i < 4; i++) {
        int m = bandA * 128 + wm * 64 + i * 16 + g;
        float t0 = te[m], t1 = te[m + 8];
        #pragma unroll
        for (int j = 0; j < 4; j++) {
            int n = bandB * 128 + wn * 32 + j * 8 + tc;
            *(float2*)(Co + (size_t)m * T_ + n) =
                make_float2(acc[i][j][0] + t0, acc[i][j][1] + t0);
            *(float2*)(Co + (size_t)(m + 8) * T_ + n) =
                make_float2(acc[i][j][2] + t1, acc[i][j][3] + t1);
        }
    }
}

// ---------------------------------------------------------------------------
// out GEMM (mma): out[s,o,t] = w_out[o,:].att[s,:,t] + b_out[o]
// ---------------------------------------------------------------------------
__global__ __launch_bounds__(256, 1)
void k_out_mma(const uint4* __restrict__ Ap, const uint2* __restrict__ Bp,
               const float* __restrict__ bias, float* __restrict__ out) {
    int s = blockIdx.z, bandA = blockIdx.y, bandB = blockIdx.x;
    const uint4* Ach = Ap + (size_t)bandA * 32 * 512;
    const uint4* Bch = (const uint4*)(Bp + (size_t)s * BATT_SLICE) + (size_t)bandB * 32 * 512;

    float acc[4][4][4] = {};
    mma_tile(Ach, Bch, 32, acc);

    int tid = threadIdx.x, wid = tid >> 5, lane = tid & 31;
    int wm = wid >> 2, wn = wid & 3;
    int g = lane >> 2, tc = (lane & 3) * 2;
    float* Co = out + (size_t)s * 256 * T_;

    #pragma unroll
    for (int i = 0; i < 4; i++) {
        int m = bandA * 128 + wm * 64 + i * 16 + g;
        float t0 = bias[m], t1 = bias[m + 8];
        #pragma unroll
        for (int j = 0; j < 4; j++) {
            int n = bandB * 128 + wn * 32 + j * 8 + tc;
            *(float2*)(Co + (size_t)m * T_ + n) =
                make_float2(acc[i][j][0] + t0, acc[i][j][1] + t0);
            *(float2*)(Co + (size_t)(m + 8) * T_ + n) =
                make_float2(acc[i][j][2] + t1, acc[i][j][3] + t1);
        }
    }
}

// ---------------------------------------------------------------------------
// SIMT fp32 GEMM body (used by ctx/apply)
// ---------------------------------------------------------------------------
struct SmemBuf {
    float As[2][BK][LDS_];
    float Bs[2][BK][LDS_];
};

template<bool AT, bool BT>
__device__ __forceinline__ void gemm_tile(const float* __restrict__ Ab, int lda,
                                          const float* __restrict__ Bb, int ldb,
                                          int K, float acc[8][8], SmemBuf& sb)
{
    const int tid = threadIdx.x;
    const int tx = tid & 15, ty = tid >> 4;
    const int tr_row = tid >> 1;
    const int tr_kc  = (tid & 1) * 4;
    const int dr_k   = tid >> 5;
    const int dr_c   = (tid & 31) * 4;

    {
        if (AT) {
            float4 v = *(const float4*)(Ab + (size_t)tr_row * lda + tr_kc);
            sb.As[0][tr_kc + 0][tr_row] = v.x;
            sb.As[0][tr_kc + 1][tr_row] = v.y;
            sb.As[0][tr_kc + 2][tr_row] = v.z;
            sb.As[0][tr_kc + 3][tr_row] = v.w;
        } else {
            *(float4*)&sb.As[0][dr_k][dr_c] =
                *(const float4*)(Ab + (size_t)dr_k * lda + dr_c);
        }
        if (BT) {
            float4 v = *(const float4*)(Bb + (size_t)tr_row * ldb + tr_kc);
            sb.Bs[0][tr_kc + 0][tr_row] = v.x;
            sb.Bs[0][tr_kc + 1][tr_row] = v.y;
            sb.Bs[0][tr_kc + 2][tr_row] = v.z;
            sb.Bs[0][tr_kc + 3][tr_row] = v.w;
        } else {
            *(float4*)&sb.Bs[0][dr_k][dr_c] =
                *(const float4*)(Bb + (size_t)dr_k * ldb + dr_c);
        }
    }
    __syncthreads();

    const int nk = K / BK;
    for (int t = 0; t < nk; t++) {
        const int cur = t & 1;
        const int nxt = cur ^ 1;
        float4 va, vb;
        const bool more = (t + 1 < nk);
        if (more) {
            const int k0 = (t + 1) * BK;
            va = AT ? *(const float4*)(Ab + (size_t)tr_row * lda + k0 + tr_kc)
                    : *(const float4*)(Ab + (size_t)(k0 + dr_k) * lda + dr_c);
            vb = BT ? *(const float4*)(Bb + (size_t)tr_row * ldb + k0 + tr_kc)
                    : *(const float4*)(Bb + (size_t)(k0 + dr_k) * ldb + dr_c);
        }
        #pragma unroll
        for (int k = 0; k < BK; k++) {
            float a[8], b[8];
            *(float4*)&a[0] = *(float4*)&sb.As[cur][k][ty * 8];
            *(float4*)&a[4] = *(float4*)&sb.As[cur][k][ty * 8 + 4];
            *(float4*)&b[0] = *(float4*)&sb.Bs[cur][k][tx * 8];
            *(float4*)&b[4] = *(float4*)&sb.Bs[cur][k][tx * 8 + 4];
            #pragma unroll
            for (int i = 0; i < 8; i++)
                #pragma unroll
                for (int j = 0; j < 8; j++)
                    acc[i][j] += a[i] * b[j];
        }
        if (more) {
            if (AT) {
                sb.As[nxt][tr_kc + 0][tr_row] = va.x;
                sb.As[nxt][tr_kc + 1][tr_row] = va.y;
                sb.As[nxt][tr_kc + 2][tr_row] = va.z;
                sb.As[nxt][tr_kc + 3][tr_row] = va.w;
            } else {
                *(float4*)&sb.As[nxt][dr_k][dr_c] = va;
            }
            if (BT) {
                sb.Bs[nxt][tr_kc + 0][tr_row] = vb.x;
                sb.Bs[nxt][tr_kc + 1][tr_row] = vb.y;
                sb.Bs[nxt][tr_kc + 2][tr_row] = vb.z;
                sb.Bs[nxt][tr_kc + 3][tr_row] = vb.w;
            } else {
                *(float4*)&sb.Bs[nxt][dr_k][dr_c] = vb;
            }
            __syncthreads();
        }
    }
}

// ---------------------------------------------------------------------------
// temb
// ---------------------------------------------------------------------------
__global__ void k_temb(const float* __restrict__ time_in,
                       const float* __restrict__ w_time,
                       const float* __restrict__ b_time) {
    int s = blockIdx.x;
    int t = threadIdx.x;
    __shared__ float m[256];
    float v = time_in[(size_t)s * 256 + t];
    float sp = (v > 20.f) ? v : log1pf(__expf(v));
    m[t] = v * tanhf(sp);
    __syncthreads();

    int warp = t >> 5, lane = t & 31;
    for (int o = warp; o < OC3; o += 8) {
        const float* w = w_time + (size_t)o * 256;
        float acc = 0.f;
        #pragma unroll 4
        for (int e = lane; e < 256; e += 32) acc += m[e] * w[e];
        #pragma unroll
        for (int off = 16; off; off >>= 1) acc += __shfl_down_sync(0xffffffffu, acc, off);
        if (lane == 0) g_temb[(size_t)s * OC3 + o] = acc + b_time[o];
    }
}

// ---------------------------------------------------------------------------
// softmax over t — one warp per row
// ---------------------------------------------------------------------------
__global__ void k_softmax2() {
    int row  = blockIdx.x * 8 + (threadIdx.x >> 5);
    int lane = threadIdx.x & 31;
    int s = row >> 9;
    int r = row & 511;
    float* p = g_qkv + (size_t)s * OC3 * T_ + (size_t)(HID + r) * T_ + lane * 8;

    float4 v0 = *(float4*)p;
    float4 v1 = *(float4*)(p + 4);
    float mx = fmaxf(fmaxf(fmaxf(v0.x, v0.y), fmaxf(v0.z, v0.w)),
                     fmaxf(fmaxf(v1.x, v1.y), fmaxf(v1.z, v1.w)));
    #pragma unroll
    for (int off = 16; off; off >>= 1)
        mx = fmaxf(mx, __shfl_xor_sync(0xffffffffu, mx, off));

    v0.x = __expf(v0.x - mx); v0.y = __expf(v0.y - mx);
    v0.z = __expf(v0.z - mx); v0.w = __expf(v0.w - mx);
    v1.x = __expf(v1.x - mx); v1.y = __expf(v1.y - mx);
    v1.z = __expf(v1.z - mx); v1.w = __expf(v1.w - mx);

    float sm = v0.x + v0.y + v0.z + v0.w + v1.x + v1.y + v1.z + v1.w;
    #pragma unroll
    for (int off = 16; off; off >>= 1)
        sm += __shfl_xor_sync(0xffffffffu, sm, off);

    float inv = 1.f / sm;
    v0.x *= inv; v0.y *= inv; v0.z *= inv; v0.w *= inv;
    v1.x *= inv; v1.y *= inv; v1.z *= inv; v1.w *= inv;
    *(float4*)p = v0;
    *(float4*)(p + 4) = v1;
}

// ---------------------------------------------------------------------------
// ctx = ksm @ v^T   (SIMT)
// ---------------------------------------------------------------------------
__global__ __launch_bounds__(256, 2)
void k_ctx2() {
    __shared__ SmemBuf sb_;
    int sb = blockIdx.z;
    int s = sb >> 2, h = sb & 3;
    const float* Ab = g_qkv + (size_t)s * OC3 * T_ + (size_t)(HID + h * C_) * T_;
    const float* Bb = g_qkv + (size_t)s * OC3 * T_ + (size_t)(2 * HID + h * C_) * T_;
    float acc[8][8] = {};
    gemm_tile<true, true>(Ab, T_, Bb, T_, T_, acc, sb_);

    int tid = threadIdx.x, tx = tid & 15, ty = tid >> 4;
    float* Co = g_ctx + (size_t)sb * C_ * C_;
    #pragma unroll
    for (int i = 0; i < 8; i++) {
        float* row = Co + (size_t)(ty * 8 + i) * C_ + tx * 8;
        *(float4*)row = make_float4(acc[i][0], acc[i][1], acc[i][2], acc[i][3]);
        *(float4*)(row + 4) = make_float4(acc[i][4], acc[i][5], acc[i][6], acc[i][7]);
    }
}

// ---------------------------------------------------------------------------
// apply: att[s, f, t] = sum_d ctx[d, e] * q[d, t]   (f = h*128 + e)   (SIMT)
// ---------------------------------------------------------------------------
__global__ __launch_bounds__(256, 2)
void k_apply2() {
    __shared__ SmemBuf sb_;
    int sb = blockIdx.z;
    int s = sb >> 2, h = sb & 3;
    int n0 = blockIdx.x * 128;
    const float* Ab = g_ctx + (size_t)sb * C_ * C_;
    const float* Bb = g_qkv + (size_t)s * OC3 * T_ + (size_t)(h * C_) * T_ + n0;
    float acc[8][8] = {};
    gemm_tile<false, false>(Ab, C_, Bb, T_, C_, acc, sb_);

    int tid = threadIdx.x, tx = tid & 15, ty = tid >> 4;
    #pragma unroll
    for (int i = 0; i < 8; i++) {
        int f = h * C_ + ty * 8 + i;
        float* row = g_att + ((size_t)s * HID + f) * T_ + n0 + tx * 8;
        *(float4*)row = make_float4(acc[i][0], acc[i][1], acc[i][2], acc[i][3]);
        *(float4*)(row + 4) = make_float4(acc[i][4], acc[i][5], acc[i][6], acc[i][7]);
    }
}

// ---------------------------------------------------------------------------
extern "C" void kernel_launch(void* const* d_in, const int* in_sizes, int n_in,
                              void* d_out, int out_size) {
    (void)in_sizes; (void)n_in; (void)out_size;
    const float* x       = (const float*)d_in[0];
    const float* time_in = (const float*)d_in[1];
    const float* w_qkv   = (const float*)d_in[2];
    const float* w_time  = (const float*)d_in[3];
    const float* b_time  = (const float*)d_in[4];
    const float* w_out   = (const float*)d_in[5];
    const float* b_out   = (const float*)d_in[6];
    float* out = (float*)d_out;

    uint4* pA_qkv; cudaGetSymbolAddress((void**)&pA_qkv, gA_qkv);
    uint4* pA_out; cudaGetSymbolAddress((void**)&pA_out, gA_out);
    uint2* pB_x;   cudaGetSymbolAddress((void**)&pB_x,   gB_x);
    uint2* pB_att; cudaGetSymbolAddress((void**)&pB_att, gB_att);
    float* pAtt;   cudaGetSymbolAddress((void**)&pAtt,   g_att);

    // 1. time embedding
    k_temb<<<S_, 256>>>(time_in, w_time, b_time);

    // 2. operand conversions for qkv GEMM
    conv_A<<<192, 256>>>(w_qkv, F_, 16, pA_qkv);                 // 12 bands x 16 ksteps
    conv_Bd<<<dim3(64, S_), 256>>>(x, T_, 16, (size_t)F_ * T_, pB_x, BX_SLICE);

    // 3. qkv GEMM on tensor cores (+temb)
    k_qkv_mma<<<dim3(2, 12, S_), 256>>>(pA_qkv, pB_x);

    // 4. softmax on k part
    k_softmax2<<<(S_ * HID) / 8, 256>>>();

    // 5. attention GEMMs (SIMT)
    k_ctx2<<<dim3(1, 1, S_ * HEADS), 256>>>();
    k_apply2<<<dim3(2, 1, S_ * HEADS), 256>>>();

    // 6. operand conversions for out GEMM
    conv_A<<<64, 256>>>(w_out, HID, 32, pA_out);                 // 2 bands x 32 ksteps
    conv_Bd<<<dim3(128, S_), 256>>>(pAtt, T_, 32, (size_t)HID * T_, pB_att, BATT_SLICE);

    // 7. out GEMM on tensor cores (+bias)
    k_out_mma<<<dim3(2, 2, S_), 256>>>(pA_out, pB_att, b_out, out);
}

// round 4
// speedup vs baseline: 2.4280x; 1.1578x over previous
#include <cuda_runtime.h>
#include <cuda_bf16.h>
#include <math.h>

// Problem constants
#define B_   64
#define A_   8
#define S_   512
#define F_   256
#define T_   256
#define HID  512
#define OC3  1536
#define HEADS 4
#define C_   128

// ---------------------------------------------------------------------------
// Scratch
// ---------------------------------------------------------------------------
__device__ float g_temb[(size_t)S_ * OC3];
__device__ float g_qkv [(size_t)S_ * OC3 * T_];                 // 805 MB
__device__ float g_ctx [(size_t)S_ * HEADS * C_ * C_];          // ctxT: [sb][e][d]
__device__ float g_att [(size_t)S_ * HID * T_];                 // [s][f][t]

// Fragment-packed bf16 hi/lo operand buffers (weights + B operands of big GEMMs)
__device__ uint4 gA_qkv[(size_t)12 * 16 * 8 * 2 * 32];
__device__ uint4 gA_out[(size_t)2 * 32 * 8 * 2 * 32];
__device__ uint2 gB_x  [(size_t)S_ * 2 * 16 * 16 * 2 * 32];
__device__ uint2 gB_att[(size_t)S_ * 2 * 32 * 16 * 2 * 32];

#define BX_SLICE   ((size_t)2 * 16 * 16 * 2 * 32)
#define BATT_SLICE ((size_t)2 * 32 * 16 * 2 * 32)

// ---------------------------------------------------------------------------
// helpers
// ---------------------------------------------------------------------------
__device__ __forceinline__ unsigned bpack(float x, float y) {
    __nv_bfloat162 h = __floats2bfloat162_rn(x, y);
    return *reinterpret_cast<unsigned*>(&h);
}
__device__ __forceinline__ void bsplit(float v, float& hi, float& lo) {
    __nv_bfloat16 h = __float2bfloat16(v);
    hi = __bfloat162float(h);
    lo = v - hi;
}
__device__ __forceinline__ void mma_bf16(float* c, const uint4& a, const uint2& b) {
    asm volatile(
        "mma.sync.aligned.m16n8k16.row.col.f32.bf16.bf16.f32 "
        "{%0,%1,%2,%3}, {%4,%5,%6,%7}, {%8,%9}, {%0,%1,%2,%3};\n"
        : "+f"(c[0]), "+f"(c[1]), "+f"(c[2]), "+f"(c[3])
        : "r"(a.x), "r"(a.y), "r"(a.z), "r"(a.w), "r"(b.x), "r"(b.y));
}

// pack two fp32 pairs into hi/lo bf16x2 words
__device__ __forceinline__ void pack2(float x, float y, unsigned& hi, unsigned& lo) {
    float hx, lx, hy, ly;
    bsplit(x, hx, lx); bsplit(y, hy, ly);
    hi = bpack(hx, hy); lo = bpack(lx, ly);
}

// ---------------------------------------------------------------------------
// conv_A: fp32 [M x K] row-major -> fragment-packed bf16 hi/lo (weights)
// ---------------------------------------------------------------------------
__global__ void conv_A(const float* __restrict__ src, int lda, int Ksteps,
                       uint4* __restrict__ dst) {
    int wg   = blockIdx.x * 8 + (threadIdx.x >> 5);
    int lane = threadIdx.x & 31;
    int mf   = wg & 7;
    int ks   = (wg >> 3) % Ksteps;
    int band = wg / (8 * Ksteps);
    int g = lane >> 2, tc = (lane & 3) * 2;

    const float* p = src + (size_t)(band * 128 + mf * 16 + g) * lda + ks * 16 + tc;
    float2 p00 = *(const float2*)p;
    float2 p01 = *(const float2*)(p + 8);
    float2 p10 = *(const float2*)(p + (size_t)8 * lda);
    float2 p11 = *(const float2*)(p + (size_t)8 * lda + 8);

    uint4 hi, lo;
    pack2(p00.x, p00.y, hi.x, lo.x);
    pack2(p10.x, p10.y, hi.y, lo.y);
    pack2(p01.x, p01.y, hi.z, lo.z);
    pack2(p11.x, p11.y, hi.w, lo.w);

    size_t base = ((((size_t)band * Ksteps + ks) * 8 + mf) * 2) * 32 + lane;
    dst[base]      = hi;
    dst[base + 32] = lo;
}

// ---------------------------------------------------------------------------
// conv_Bd: fp32 [K x N] row-major (per-slice) -> fragment-packed bf16 hi/lo
// ---------------------------------------------------------------------------
__global__ void conv_Bd(const float* __restrict__ srcbase, int ldb, int Ksteps,
                        size_t src_slice_stride,
                        uint2* __restrict__ dstbase, size_t dst_slice_stride) {
    int s = blockIdx.y;
    const float* src = srcbase + (size_t)s * src_slice_stride;
    uint2* dst = dstbase + (size_t)s * dst_slice_stride;

    int wg   = blockIdx.x * 8 + (threadIdx.x >> 5);
    int lane = threadIdx.x & 31;
    int nf   = wg & 15;
    int ks   = (wg >> 4) % Ksteps;
    int band = wg / (16 * Ksteps);
    int g = lane >> 2, tc = (lane & 3) * 2;

    int n = band * 128 + nf * 8 + g;
    const float* p = src + (size_t)(ks * 16 + tc) * ldb + n;
    float v0 = p[0];
    float v1 = p[(size_t)ldb];
    float v2 = p[(size_t)8 * ldb];
    float v3 = p[(size_t)9 * ldb];

    unsigned h0, l0, h1, l1;
    pack2(v0, v1, h0, l0);
    pack2(v2, v3, h1, l1);

    size_t base = ((((size_t)band * Ksteps + ks) * 16 + nf) * 2) * 32 + lane;
    dst[base]      = make_uint2(h0, h1);
    dst[base + 32] = make_uint2(l0, l1);
}

// ---------------------------------------------------------------------------
// mma tile core (pre-packed operands): 128x128 CTA tile, 8 warps (2x4)
// ---------------------------------------------------------------------------
__device__ __forceinline__ void mma_tile(const uint4* __restrict__ Achunks,
                                         const uint4* __restrict__ Bchunks,
                                         int Ksteps, float acc[4][4][4]) {
    __shared__ uint4 sA[2][512];
    __shared__ uint4 sB[2][512];

    int tid = threadIdx.x;
    int wid = tid >> 5, lane = tid & 31;
    int wm = wid >> 2, wn = wid & 3;

    sA[0][tid] = Achunks[tid]; sA[0][tid + 256] = Achunks[tid + 256];
    sB[0][tid] = Bchunks[tid]; sB[0][tid + 256] = Bchunks[tid + 256];
    __syncthreads();

    for (int ks = 0; ks < Ksteps; ks++) {
        int cur = ks & 1, nxt = cur ^ 1;
        uint4 na0, na1, nb0, nb1;
        bool more = (ks + 1 < Ksteps);
        if (more) {
            const uint4* An = Achunks + (size_t)(ks + 1) * 512;
            const uint4* Bn = Bchunks + (size_t)(ks + 1) * 512;
            na0 = An[tid]; na1 = An[tid + 256];
            nb0 = Bn[tid]; nb1 = Bn[tid + 256];
        }

        uint4 a[4][2];
        uint2 b[4][2];
        const uint4* sa  = &sA[cur][0];
        const uint2* sbp = (const uint2*)&sB[cur][0];
        #pragma unroll
        for (int i = 0; i < 4; i++) {
            int mf = wm * 4 + i;
            a[i][0] = sa[(mf * 2 + 0) * 32 + lane];
            a[i][1] = sa[(mf * 2 + 1) * 32 + lane];
        }
        #pragma unroll
        for (int j = 0; j < 4; j++) {
            int nf = wn * 4 + j;
            b[j][0] = sbp[(nf * 2 + 0) * 32 + lane];
            b[j][1] = sbp[(nf * 2 + 1) * 32 + lane];
        }
        #pragma unroll
        for (int i = 0; i < 4; i++)
            #pragma unroll
            for (int j = 0; j < 4; j++) {
                mma_bf16(acc[i][j], a[i][0], b[j][0]);
                mma_bf16(acc[i][j], a[i][0], b[j][1]);
                mma_bf16(acc[i][j], a[i][1], b[j][0]);
            }

        if (more) {
            sA[nxt][tid] = na0; sA[nxt][tid + 256] = na1;
            sB[nxt][tid] = nb0; sB[nxt][tid + 256] = nb1;
            __syncthreads();
        }
    }
}

// ---------------------------------------------------------------------------
// qkv GEMM (mma)
// ---------------------------------------------------------------------------
__global__ __launch_bounds__(256, 1)
void k_qkv_mma(const uint4* __restrict__ Ap, const uint2* __restrict__ Bp) {
    int s = blockIdx.z, bandA = blockIdx.y, bandB = blockIdx.x;
    const uint4* Ach = Ap + (size_t)bandA * 16 * 512;
    const uint4* Bch = (const uint4*)(Bp + (size_t)s * BX_SLICE) + (size_t)bandB * 16 * 512;

    float acc[4][4][4] = {};
    mma_tile(Ach, Bch, 16, acc);

    int tid = threadIdx.x, wid = tid >> 5, lane = tid & 31;
    int wm = wid >> 2, wn = wid & 3;
    int g = lane >> 2, tc = (lane & 3) * 2;
    float* Co = g_qkv + (size_t)s * OC3 * T_;
    const float* te = g_temb + (size_t)s * OC3;

    #pragma unroll
    for (int i = 0; i < 4; i++) {
        int m = bandA * 128 + wm * 64 + i * 16 + g;
        float t0 = te[m], t1 = te[m + 8];
        #pragma unroll
        for (int j = 0; j < 4; j++) {
            int n = bandB * 128 + wn * 32 + j * 8 + tc;
            *(float2*)(Co + (size_t)m * T_ + n) =
                make_float2(acc[i][j][0] + t0, acc[i][j][1] + t0);
            *(float2*)(Co + (size_t)(m + 8) * T_ + n) =
                make_float2(acc[i][j][2] + t1, acc[i][j][3] + t1);
        }
    }
}

// ---------------------------------------------------------------------------
// out GEMM (mma)
// ---------------------------------------------------------------------------
__global__ __launch_bounds__(256, 1)
void k_out_mma(const uint4* __restrict__ Ap, const uint2* __restrict__ Bp,
               const float* __restrict__ bias, float* __restrict__ out) {
    int s = blockIdx.z, bandA = blockIdx.y, bandB = blockIdx.x;
    const uint4* Ach = Ap + (size_t)bandA * 32 * 512;
    const uint4* Bch = (const uint4*)(Bp + (size_t)s * BATT_SLICE) + (size_t)bandB * 32 * 512;

    float acc[4][4][4] = {};
    mma_tile(Ach, Bch, 32, acc);

    int tid = threadIdx.x, wid = tid >> 5, lane = tid & 31;
    int wm = wid >> 2, wn = wid & 3;
    int g = lane >> 2, tc = (lane & 3) * 2;
    float* Co = out + (size_t)s * 256 * T_;

    #pragma unroll
    for (int i = 0; i < 4; i++) {
        int m = bandA * 128 + wm * 64 + i * 16 + g;
        float t0 = bias[m], t1 = bias[m + 8];
        #pragma unroll
        for (int j = 0; j < 4; j++) {
            int n = bandB * 128 + wn * 32 + j * 8 + tc;
            *(float2*)(Co + (size_t)m * T_ + n) =
                make_float2(acc[i][j][0] + t0, acc[i][j][1] + t0);
            *(float2*)(Co + (size_t)(m + 8) * T_ + n) =
                make_float2(acc[i][j][2] + t1, acc[i][j][3] + t1);
        }
    }
}

// ---------------------------------------------------------------------------
// Fused-staging mma GEMM: stages fp32 A [M,K] row-major and B (either
// [N,K] "NK" or [K,N] "KN" row-major) into frag-packed hi/lo smem each
// k-step, then does the 3-pass mma. CTA tile 128x128, 8 warps.
//   - warp w stages A frag mf=w and B frags nf=2w, 2w+1
// ---------------------------------------------------------------------------
template<bool B_IS_NK>
__device__ __forceinline__ void mma_tile_stage(const float* __restrict__ Ag, int lda,
                                               const float* __restrict__ Bg, int ldb,
                                               int Ksteps, float acc[4][4][4]) {
    __shared__ uint4 sA[2][512];
    __shared__ uint4 sB[2][512];

    int tid = threadIdx.x;
    int wid = tid >> 5, lane = tid & 31;
    int wm = wid >> 2, wn = wid & 3;
    int g = lane >> 2, tc = (lane & 3) * 2;

    // --- staging helpers ---
    // A frag (16x16) for this warp: rows mf*16+{g,g+8}, cols ks*16+{tc,tc+8}
    const float* Ap0 = Ag + (size_t)(wid * 16 + g) * lda + tc;         // mf = wid
    // B frags nf = 2*wid, 2*wid+1
    int n0b = wid * 16 + g;           // nf=2w covers rows 2w*8..  (2 frags = 16 rows)

    auto stage = [&](int ks, int buf) {
        int kof = ks * 16;
        // A
        {
            const float* p = Ap0 + kof;
            float2 p00 = *(const float2*)p;
            float2 p01 = *(const float2*)(p + 8);
            float2 p10 = *(const float2*)(p + (size_t)8 * lda);
            float2 p11 = *(const float2*)(p + (size_t)8 * lda + 8);
            uint4 hi, lo;
            pack2(p00.x, p00.y, hi.x, lo.x);
            pack2(p10.x, p10.y, hi.y, lo.y);
            pack2(p01.x, p01.y, hi.z, lo.z);
            pack2(p11.x, p11.y, hi.w, lo.w);
            sA[buf][(wid * 2 + 0) * 32 + lane] = hi;
            sA[buf][(wid * 2 + 1) * 32 + lane] = lo;
        }
        // B: two 16x8 frags; frag f covers n rows [ (2*wid+f)*8, +8 )
        uint2* sbp = (uint2*)&sB[buf][0];
        #pragma unroll
        for (int f = 0; f < 2; f++) {
            int n = (wid * 2 + f) * 8 + g;
            float v0, v1, v2, v3;
            if (B_IS_NK) {
                const float* p = Bg + (size_t)n * ldb + kof + tc;
                float2 a0 = *(const float2*)p;
                float2 a1 = *(const float2*)(p + 8);
                v0 = a0.x; v1 = a0.y; v2 = a1.x; v3 = a1.y;
            } else {
                const float* p = Bg + (size_t)(kof + tc) * ldb + n;
                v0 = p[0];
                v1 = p[(size_t)ldb];
                v2 = p[(size_t)8 * ldb];
                v3 = p[(size_t)9 * ldb];
            }
            unsigned h0, l0, h1, l1;
            pack2(v0, v1, h0, l0);
            pack2(v2, v3, h1, l1);
            int nf = wid * 2 + f;
            sbp[(nf * 2 + 0) * 32 + lane] = make_uint2(h0, h1);
            sbp[(nf * 2 + 1) * 32 + lane] = make_uint2(l0, l1);
        }
    };

    stage(0, 0);
    __syncthreads();

    for (int ks = 0; ks < Ksteps; ks++) {
        int cur = ks & 1, nxt = cur ^ 1;

        uint4 a[4][2];
        uint2 b[4][2];
        const uint4* sa  = &sA[cur][0];
        const uint2* sbp = (const uint2*)&sB[cur][0];
        #pragma unroll
        for (int i = 0; i < 4; i++) {
            int mf = wm * 4 + i;
            a[i][0] = sa[(mf * 2 + 0) * 32 + lane];
            a[i][1] = sa[(mf * 2 + 1) * 32 + lane];
        }
        #pragma unroll
        for (int j = 0; j < 4; j++) {
            int nf = wn * 4 + j;
            b[j][0] = sbp[(nf * 2 + 0) * 32 + lane];
            b[j][1] = sbp[(nf * 2 + 1) * 32 + lane];
        }
        #pragma unroll
        for (int i = 0; i < 4; i++)
            #pragma unroll
            for (int j = 0; j < 4; j++) {
                mma_bf16(acc[i][j], a[i][0], b[j][0]);
                mma_bf16(acc[i][j], a[i][0], b[j][1]);
                mma_bf16(acc[i][j], a[i][1], b[j][0]);
            }

        if (ks + 1 < Ksteps) {
            stage(ks + 1, nxt);
            __syncthreads();
        }
    }
}

// ---------------------------------------------------------------------------
// ctx (mma): ctxT[sb][e][d] = sum_t v[e,t] * ksm[d,t]
//   A = v   [e][t]  (M=128, K=256, row-major, lda=T_)
//   B = ksm [d][t]  -> B[k=t][n=d] = ksm[n][k]  (NK layout)
// ---------------------------------------------------------------------------
__global__ __launch_bounds__(256, 1)
void k_ctx_mma() {
    int sb = blockIdx.z;
    int s = sb >> 2, h = sb & 3;
    const float* v   = g_qkv + (size_t)s * OC3 * T_ + (size_t)(2 * HID + h * C_) * T_;
    const float* ksm = g_qkv + (size_t)s * OC3 * T_ + (size_t)(HID + h * C_) * T_;

    float acc[4][4][4] = {};
    mma_tile_stage<true>(v, T_, ksm, T_, 16, acc);

    int tid = threadIdx.x, wid = tid >> 5, lane = tid & 31;
    int wm = wid >> 2, wn = wid & 3;
    int g = lane >> 2, tc = (lane & 3) * 2;
    float* Co = g_ctx + (size_t)sb * C_ * C_;

    #pragma unroll
    for (int i = 0; i < 4; i++) {
        int m = wm * 64 + i * 16 + g;
        #pragma unroll
        for (int j = 0; j < 4; j++) {
            int n = wn * 32 + j * 8 + tc;
            *(float2*)(Co + (size_t)m * C_ + n) = make_float2(acc[i][j][0], acc[i][j][1]);
            *(float2*)(Co + (size_t)(m + 8) * C_ + n) = make_float2(acc[i][j][2], acc[i][j][3]);
        }
    }
}

// ---------------------------------------------------------------------------
// apply (mma): att[s][h*C_+e][t] = sum_d ctxT[e][d] * q[d][t]
//   A = ctxT [e][d] (M=128, K=128, lda=C_)
//   B = q    [d][t] (KN layout, ldb=T_), N split over 2 CTAs
// ---------------------------------------------------------------------------
__global__ __launch_bounds__(256, 1)
void k_apply_mma() {
    int sb = blockIdx.z;
    int s = sb >> 2, h = sb & 3;
    int n0 = blockIdx.x * 128;
    const float* ctxT = g_ctx + (size_t)sb * C_ * C_;
    const float* q = g_qkv + (size_t)s * OC3 * T_ + (size_t)(h * C_) * T_ + n0;

    float acc[4][4][4] = {};
    mma_tile_stage<false>(ctxT, C_, q, T_, 8, acc);

    int tid = threadIdx.x, wid = tid >> 5, lane = tid & 31;
    int wm = wid >> 2, wn = wid & 3;
    int g = lane >> 2, tc = (lane & 3) * 2;

    #pragma unroll
    for (int i = 0; i < 4; i++) {
        int e = wm * 64 + i * 16 + g;
        float* r0 = g_att + ((size_t)s * HID + h * C_ + e) * T_ + n0;
        float* r1 = g_att + ((size_t)s * HID + h * C_ + e + 8) * T_ + n0;
        #pragma unroll
        for (int j = 0; j < 4; j++) {
            int n = wn * 32 + j * 8 + tc;
            *(float2*)(r0 + n) = make_float2(acc[i][j][0], acc[i][j][1]);
            *(float2*)(r1 + n) = make_float2(acc[i][j][2], acc[i][j][3]);
        }
    }
}

// ---------------------------------------------------------------------------
// temb
// ---------------------------------------------------------------------------
__global__ void k_temb(const float* __restrict__ time_in,
                       const float* __restrict__ w_time,
                       const float* __restrict__ b_time) {
    int s = blockIdx.x;
    int t = threadIdx.x;
    __shared__ float m[256];
    float v = time_in[(size_t)s * 256 + t];
    float sp = (v > 20.f) ? v : log1pf(__expf(v));
    m[t] = v * tanhf(sp);
    __syncthreads();

    int warp = t >> 5, lane = t & 31;
    for (int o = warp; o < OC3; o += 8) {
        const float* w = w_time + (size_t)o * 256;
        float acc = 0.f;
        #pragma unroll 4
        for (int e = lane; e < 256; e += 32) acc += m[e] * w[e];
        #pragma unroll
        for (int off = 16; off; off >>= 1) acc += __shfl_down_sync(0xffffffffu, acc, off);
        if (lane == 0) g_temb[(size_t)s * OC3 + o] = acc + b_time[o];
    }
}

// ---------------------------------------------------------------------------
// softmax over t — one warp per row
// ---------------------------------------------------------------------------
__global__ void k_softmax2() {
    int row  = blockIdx.x * 8 + (threadIdx.x >> 5);
    int lane = threadIdx.x & 31;
    int s = row >> 9;
    int r = row & 511;
    float* p = g_qkv + (size_t)s * OC3 * T_ + (size_t)(HID + r) * T_ + lane * 8;

    float4 v0 = *(float4*)p;
    float4 v1 = *(float4*)(p + 4);
    float mx = fmaxf(fmaxf(fmaxf(v0.x, v0.y), fmaxf(v0.z, v0.w)),
                     fmaxf(fmaxf(v1.x, v1.y), fmaxf(v1.z, v1.w)));
    #pragma unroll
    for (int off = 16; off; off >>= 1)
        mx = fmaxf(mx, __shfl_xor_sync(0xffffffffu, mx, off));

    v0.x = __expf(v0.x - mx); v0.y = __expf(v0.y - mx);
    v0.z = __expf(v0.z - mx); v0.w = __expf(v0.w - mx);
    v1.x = __expf(v1.x - mx); v1.y = __expf(v1.y - mx);
    v1.z = __expf(v1.z - mx); v1.w = __expf(v1.w - mx);

    float sm = v0.x + v0.y + v0.z + v0.w + v1.x + v1.y + v1.z + v1.w;
    #pragma unroll
    for (int off = 16; off; off >>= 1)
        sm += __shfl_xor_sync(0xffffffffu, sm, off);

    float inv = 1.f / sm;
    v0.x *= inv; v0.y *= inv; v0.z *= inv; v0.w *= inv;
    v1.x *= inv; v1.y *= inv; v1.z *= inv; v1.w *= inv;
    *(float4*)p = v0;
    *(float4*)(p + 4) = v1;
}

// ---------------------------------------------------------------------------
extern "C" void kernel_launch(void* const* d_in, const int* in_sizes, int n_in,
                              void* d_out, int out_size) {
    (void)in_sizes; (void)n_in; (void)out_size;
    const float* x       = (const float*)d_in[0];
    const float* time_in = (const float*)d_in[1];
    const float* w_qkv   = (const float*)d_in[2];
    const float* w_time  = (const float*)d_in[3];
    const float* b_time  = (const float*)d_in[4];
    const float* w_out   = (const float*)d_in[5];
    const float* b_out   = (const float*)d_in[6];
    float* out = (float*)d_out;

    uint4* pA_qkv; cudaGetSymbolAddress((void**)&pA_qkv, gA_qkv);
    uint4* pA_out; cudaGetSymbolAddress((void**)&pA_out, gA_out);
    uint2* pB_x;   cudaGetSymbolAddress((void**)&pB_x,   gB_x);
    uint2* pB_att; cudaGetSymbolAddress((void**)&pB_att, gB_att);
    float* pAtt;   cudaGetSymbolAddress((void**)&pAtt,   g_att);

    k_temb<<<S_, 256>>>(time_in, w_time, b_time);

    conv_A<<<192, 256>>>(w_qkv, F_, 16, pA_qkv);
    conv_Bd<<<dim3(64, S_), 256>>>(x, T_, 16, (size_t)F_ * T_, pB_x, BX_SLICE);

    k_qkv_mma<<<dim3(2, 12, S_), 256>>>(pA_qkv, pB_x);

    k_softmax2<<<(S_ * HID) / 8, 256>>>();

    k_ctx_mma<<<dim3(1, 1, S_ * HEADS), 256>>>();
    k_apply_mma<<<dim3(2, 1, S_ * HEADS), 256>>>();

    conv_A<<<64, 256>>>(w_out, HID, 32, pA_out);
    conv_Bd<<<dim3(128, S_), 256>>>(pAtt, T_, 32, (size_t)HID * T_, pB_att, BATT_SLICE);

    k_out_mma<<<dim3(2, 2, S_), 256>>>(pA_out, pB_att, b_out, out);
}

// round 5
// speedup vs baseline: 2.9970x; 1.2344x over previous
#include <cuda_runtime.h>
#include <cuda_bf16.h>
#include <math.h>

// Problem constants
#define B_   64
#define A_   8
#define S_   512
#define F_   256
#define T_   256
#define HID  512
#define OC3  1536
#define HEADS 4
#define C_   128

// ---------------------------------------------------------------------------
// Scratch
// ---------------------------------------------------------------------------
__device__ float g_temb[(size_t)S_ * OC3];
__device__ float g_qkv [(size_t)S_ * OC3 * T_];                 // 805 MB
__device__ float g_kmax[(size_t)S_ * HID];
__device__ float g_kinv[(size_t)S_ * HID];
__device__ uint2 g_ctxp[(size_t)S_ * HEADS * 8192];             // packed ctx b-frags

// Fragment-packed bf16 hi/lo operand buffers
__device__ uint4 gA_qkv[(size_t)12 * 16 * 8 * 2 * 32];
__device__ uint4 gA_out[(size_t)2 * 32 * 8 * 2 * 32];
__device__ uint2 gB_x  [(size_t)S_ * 2 * 16 * 16 * 2 * 32];
__device__ uint2 gB_att[(size_t)S_ * 2 * 32 * 16 * 2 * 32];     // written by applyT

#define BX_SLICE   ((size_t)2 * 16 * 16 * 2 * 32)
#define BATT_SLICE ((size_t)2 * 32 * 16 * 2 * 32)

// ---------------------------------------------------------------------------
// helpers
// ---------------------------------------------------------------------------
__device__ __forceinline__ unsigned bpack(float x, float y) {
    __nv_bfloat162 h = __floats2bfloat162_rn(x, y);
    return *reinterpret_cast<unsigned*>(&h);
}
__device__ __forceinline__ void bsplit(float v, float& hi, float& lo) {
    __nv_bfloat16 h = __float2bfloat16(v);
    hi = __bfloat162float(h);
    lo = v - hi;
}
__device__ __forceinline__ void pack2(float x, float y, unsigned& hi, unsigned& lo) {
    float hx, lx, hy, ly;
    bsplit(x, hx, lx); bsplit(y, hy, ly);
    hi = bpack(hx, hy); lo = bpack(lx, ly);
}
__device__ __forceinline__ void mma_bf16(float* c, const uint4& a, const uint2& b) {
    asm volatile(
        "mma.sync.aligned.m16n8k16.row.col.f32.bf16.bf16.f32 "
        "{%0,%1,%2,%3}, {%4,%5,%6,%7}, {%8,%9}, {%0,%1,%2,%3};\n"
        : "+f"(c[0]), "+f"(c[1]), "+f"(c[2]), "+f"(c[3])
        : "r"(a.x), "r"(a.y), "r"(a.z), "r"(a.w), "r"(b.x), "r"(b.y));
}

// cp.async (LDGSTS)
__device__ __forceinline__ void cp16(uint4* smem, const uint4* gmem) {
    unsigned sa = (unsigned)__cvta_generic_to_shared(smem);
    asm volatile("cp.async.cg.shared.global [%0], [%1], 16;\n" :: "r"(sa), "l"(gmem));
}
__device__ __forceinline__ void cp_commit() { asm volatile("cp.async.commit_group;\n" ::); }
__device__ __forceinline__ void cp_wait1()  { asm volatile("cp.async.wait_group 1;\n" ::); }
__device__ __forceinline__ void cp_wait0()  { asm volatile("cp.async.wait_group 0;\n" ::); }

// shared frag-load + 3-pass mma for one k-step (warp tile 64x32)
__device__ __forceinline__ void frag_mma(const uint4* sa, const uint2* sbp,
                                         int wm, int wn, int lane, float acc[4][4][4]) {
    uint4 a[4][2]; uint2 b[4][2];
    #pragma unroll
    for (int i = 0; i < 4; i++) {
        int mf = wm * 4 + i;
        a[i][0] = sa[(mf * 2 + 0) * 32 + lane];
        a[i][1] = sa[(mf * 2 + 1) * 32 + lane];
    }
    #pragma unroll
    for (int j = 0; j < 4; j++) {
        int nf = wn * 4 + j;
        b[j][0] = sbp[(nf * 2 + 0) * 32 + lane];
        b[j][1] = sbp[(nf * 2 + 1) * 32 + lane];
    }
    #pragma unroll
    for (int i = 0; i < 4; i++)
        #pragma unroll
        for (int j = 0; j < 4; j++) {
            mma_bf16(acc[i][j], a[i][0], b[j][0]);
            mma_bf16(acc[i][j], a[i][0], b[j][1]);
            mma_bf16(acc[i][j], a[i][1], b[j][0]);
        }
}

// pack a 16(row)x16(col-pair) block of accumulators into B-frag words
// a0 = acc for col-pair at k offset <8 (b.x half), a1 = k offset >=8 (b.y half)
__device__ __forceinline__ void store_bfrag(uint2* dst, size_t cb, int nf0, int lane,
                                            const float* a0, const float* a1) {
    unsigned h00,l00,h01,l01,h10,l10,h11,l11;
    pack2(a0[0], a0[1], h00, l00); pack2(a1[0], a1[1], h01, l01);
    pack2(a0[2], a0[3], h10, l10); pack2(a1[2], a1[3], h11, l11);
    dst[cb + (size_t)(nf0 * 2 + 0) * 32 + lane] = make_uint2(h00, h01);
    dst[cb + (size_t)(nf0 * 2 + 1) * 32 + lane] = make_uint2(l00, l01);
    dst[cb + (size_t)((nf0 + 1) * 2 + 0) * 32 + lane] = make_uint2(h10, h11);
    dst[cb + (size_t)((nf0 + 1) * 2 + 1) * 32 + lane] = make_uint2(l10, l11);
}

// ---------------------------------------------------------------------------
// conv_A: fp32 [M x K] row-major -> fragment-packed bf16 hi/lo (weights)
// ---------------------------------------------------------------------------
__global__ void conv_A(const float* __restrict__ src, int lda, int Ksteps,
                       uint4* __restrict__ dst) {
    int wg   = blockIdx.x * 8 + (threadIdx.x >> 5);
    int lane = threadIdx.x & 31;
    int mf   = wg & 7;
    int ks   = (wg >> 3) % Ksteps;
    int band = wg / (8 * Ksteps);
    int g = lane >> 2, tc = (lane & 3) * 2;

    const float* p = src + (size_t)(band * 128 + mf * 16 + g) * lda + ks * 16 + tc;
    float2 p00 = *(const float2*)p;
    float2 p01 = *(const float2*)(p + 8);
    float2 p10 = *(const float2*)(p + (size_t)8 * lda);
    float2 p11 = *(const float2*)(p + (size_t)8 * lda + 8);

    uint4 hi, lo;
    pack2(p00.x, p00.y, hi.x, lo.x);
    pack2(p10.x, p10.y, hi.y, lo.y);
    pack2(p01.x, p01.y, hi.z, lo.z);
    pack2(p11.x, p11.y, hi.w, lo.w);

    size_t base = ((((size_t)band * Ksteps + ks) * 8 + mf) * 2) * 32 + lane;
    dst[base]      = hi;
    dst[base + 32] = lo;
}

// ---------------------------------------------------------------------------
// conv_Bd: fp32 [K x N] row-major (per-slice) -> fragment-packed bf16 hi/lo
// ---------------------------------------------------------------------------
__global__ void conv_Bd(const float* __restrict__ srcbase, int ldb, int Ksteps,
                        size_t src_slice_stride,
                        uint2* __restrict__ dstbase, size_t dst_slice_stride) {
    int s = blockIdx.y;
    const float* src = srcbase + (size_t)s * src_slice_stride;
    uint2* dst = dstbase + (size_t)s * dst_slice_stride;

    int wg   = blockIdx.x * 8 + (threadIdx.x >> 5);
    int lane = threadIdx.x & 31;
    int nf   = wg & 15;
    int ks   = (wg >> 4) % Ksteps;
    int band = wg / (16 * Ksteps);
    int g = lane >> 2, tc = (lane & 3) * 2;

    int n = band * 128 + nf * 8 + g;
    const float* p = src + (size_t)(ks * 16 + tc) * ldb + n;
    float v0 = p[0];
    float v1 = p[(size_t)ldb];
    float v2 = p[(size_t)8 * ldb];
    float v3 = p[(size_t)9 * ldb];

    unsigned h0, l0, h1, l1;
    pack2(v0, v1, h0, l0);
    pack2(v2, v3, h1, l1);

    size_t base = ((((size_t)band * Ksteps + ks) * 16 + nf) * 2) * 32 + lane;
    dst[base]      = make_uint2(h0, h1);
    dst[base + 32] = make_uint2(l0, l1);
}

// ---------------------------------------------------------------------------
// mma tile (prepacked operands), 3-stage cp.async pipeline
// ---------------------------------------------------------------------------
__device__ __forceinline__ void mma_tile3(const uint4* __restrict__ Achunks,
                                          const uint4* __restrict__ Bchunks,
                                          int Ksteps, float acc[4][4][4]) {
    __shared__ uint4 sA[3][512];
    __shared__ uint4 sB[3][512];
    int tid = threadIdx.x, wid = tid >> 5, lane = tid & 31;
    int wm = wid >> 2, wn = wid & 3;

    auto issue = [&](int ks) {
        int st = ks % 3;
        const uint4* A = Achunks + (size_t)ks * 512;
        const uint4* B = Bchunks + (size_t)ks * 512;
        cp16(&sA[st][tid], A + tid); cp16(&sA[st][tid + 256], A + tid + 256);
        cp16(&sB[st][tid], B + tid); cp16(&sB[st][tid + 256], B + tid + 256);
        cp_commit();
    };
    issue(0);
    issue(1);

    for (int ks = 0; ks < Ksteps; ks++) {
        if (ks + 1 < Ksteps) cp_wait1(); else cp_wait0();
        __syncthreads();
        if (ks + 2 < Ksteps) issue(ks + 2);
        frag_mma(&sA[ks % 3][0], (const uint2*)&sB[ks % 3][0], wm, wn, lane, acc);
    }
}

// ---------------------------------------------------------------------------
// qkv GEMM (mma, prepacked)
// ---------------------------------------------------------------------------
__global__ __launch_bounds__(256, 2)
void k_qkv_mma(const uint4* __restrict__ Ap, const uint2* __restrict__ Bp) {
    int s = blockIdx.z, bandA = blockIdx.y, bandB = blockIdx.x;
    const uint4* Ach = Ap + (size_t)bandA * 16 * 512;
    const uint4* Bch = (const uint4*)(Bp + (size_t)s * BX_SLICE) + (size_t)bandB * 16 * 512;

    float acc[4][4][4] = {};
    mma_tile3(Ach, Bch, 16, acc);

    int tid = threadIdx.x, wid = tid >> 5, lane = tid & 31;
    int wm = wid >> 2, wn = wid & 3;
    int g = lane >> 2, tc = (lane & 3) * 2;
    float* Co = g_qkv + (size_t)s * OC3 * T_;
    const float* te = g_temb + (size_t)s * OC3;

    #pragma unroll
    for (int i = 0; i < 4; i++) {
        int m = bandA * 128 + wm * 64 + i * 16 + g;
        float t0 = te[m], t1 = te[m + 8];
        #pragma unroll
        for (int j = 0; j < 4; j++) {
            int n = bandB * 128 + wn * 32 + j * 8 + tc;
            *(float2*)(Co + (size_t)m * T_ + n) =
                make_float2(acc[i][j][0] + t0, acc[i][j][1] + t0);
            *(float2*)(Co + (size_t)(m + 8) * T_ + n) =
                make_float2(acc[i][j][2] + t1, acc[i][j][3] + t1);
        }
    }
}

// ---------------------------------------------------------------------------
// out GEMM (mma, prepacked)
// ---------------------------------------------------------------------------
__global__ __launch_bounds__(256, 2)
void k_out_mma(const uint4* __restrict__ Ap, const uint2* __restrict__ Bp,
               const float* __restrict__ bias, float* __restrict__ out) {
    int s = blockIdx.z, bandA = blockIdx.y, bandB = blockIdx.x;
    const uint4* Ach = Ap + (size_t)bandA * 32 * 512;
    const uint4* Bch = (const uint4*)(Bp + (size_t)s * BATT_SLICE) + (size_t)bandB * 32 * 512;

    float acc[4][4][4] = {};
    mma_tile3(Ach, Bch, 32, acc);

    int tid = threadIdx.x, wid = tid >> 5, lane = tid & 31;
    int wm = wid >> 2, wn = wid & 3;
    int g = lane >> 2, tc = (lane & 3) * 2;
    float* Co = out + (size_t)s * 256 * T_;

    #pragma unroll
    for (int i = 0; i < 4; i++) {
        int m = bandA * 128 + wm * 64 + i * 16 + g;
        float t0 = bias[m], t1 = bias[m + 8];
        #pragma unroll
        for (int j = 0; j < 4; j++) {
            int n = bandB * 128 + wn * 32 + j * 8 + tc;
            *(float2*)(Co + (size_t)m * T_ + n) =
                make_float2(acc[i][j][0] + t0, acc[i][j][1] + t0);
            *(float2*)(Co + (size_t)(m + 8) * T_ + n) =
                make_float2(acc[i][j][2] + t1, acc[i][j][3] + t1);
        }
    }
}

// ---------------------------------------------------------------------------
// k stats: per k-row max and 1/sum(exp(v-max))
// ---------------------------------------------------------------------------
__global__ void k_kstats() {
    int row  = blockIdx.x * 8 + (threadIdx.x >> 5);
    int lane = threadIdx.x & 31;
    int s = row >> 9, r = row & 511;
    const float* p = g_qkv + (size_t)s * OC3 * T_ + (size_t)(HID + r) * T_ + lane * 8;

    float4 v0 = *(const float4*)p;
    float4 v1 = *(const float4*)(p + 4);
    float mx = fmaxf(fmaxf(fmaxf(v0.x, v0.y), fmaxf(v0.z, v0.w)),
                     fmaxf(fmaxf(v1.x, v1.y), fmaxf(v1.z, v1.w)));
    #pragma unroll
    for (int off = 16; off; off >>= 1)
        mx = fmaxf(mx, __shfl_xor_sync(0xffffffffu, mx, off));

    float sm = __expf(v0.x - mx) + __expf(v0.y - mx) + __expf(v0.z - mx) + __expf(v0.w - mx)
             + __expf(v1.x - mx) + __expf(v1.y - mx) + __expf(v1.z - mx) + __expf(v1.w - mx);
    #pragma unroll
    for (int off = 16; off; off >>= 1)
        sm += __shfl_xor_sync(0xffffffffu, sm, off);

    if (lane == 0) {
        g_kmax[row] = mx;
        g_kinv[row] = 1.f / sm;
    }
}

// ---------------------------------------------------------------------------
// ctx: ctxT[e][d] = sum_t v[e,t] * softmax(k)[d,t] — softmax fused in staging
// epilogue writes packed bf16 B-frags (for applyT) to g_ctxp
// ---------------------------------------------------------------------------
__global__ __launch_bounds__(256, 1)
void k_ctx_mma() {
    __shared__ uint4 sA[2][512];
    __shared__ uint4 sB[2][512];
    int sb = blockIdx.x, s = sb >> 2, h = sb & 3;
    int tid = threadIdx.x, wid = tid >> 5, lane = tid & 31;
    int wm = wid >> 2, wn = wid & 3, g = lane >> 2, tc = (lane & 3) * 2;

    const float* vmat = g_qkv + (size_t)s * OC3 * T_ + (size_t)(2 * HID + h * C_) * T_;
    const float* kraw = g_qkv + (size_t)s * OC3 * T_ + (size_t)(HID + h * C_) * T_;
    int rb = s * HID + h * C_;
    float mx0 = g_kmax[rb + wid * 16 + g],     iv0 = g_kinv[rb + wid * 16 + g];
    float mx1 = g_kmax[rb + wid * 16 + 8 + g], iv1 = g_kinv[rb + wid * 16 + 8 + g];

    const float* Ap0 = vmat + (size_t)(wid * 16 + g) * T_ + tc;
    const float* Bp0 = kraw + (size_t)(wid * 16 + g) * T_ + tc;
    const float* Bp1 = kraw + (size_t)(wid * 16 + 8 + g) * T_ + tc;

    float2 a00, a01, a10, a11;
    float b0[4], b1[4];
    auto gload = [&](int ks) {
        const float* p = Ap0 + ks * 16;
        a00 = *(const float2*)p;
        a01 = *(const float2*)(p + 8);
        a10 = *(const float2*)(p + (size_t)8 * T_);
        a11 = *(const float2*)(p + (size_t)8 * T_ + 8);
        const float* q0 = Bp0 + ks * 16;
        b0[0] = q0[0]; b0[1] = q0[1]; b0[2] = q0[8]; b0[3] = q0[9];
        const float* q1 = Bp1 + ks * 16;
        b1[0] = q1[0]; b1[1] = q1[1]; b1[2] = q1[8]; b1[3] = q1[9];
    };
    auto sstore = [&](int buf) {
        uint4 hi, lo;
        pack2(a00.x, a00.y, hi.x, lo.x);
        pack2(a10.x, a10.y, hi.y, lo.y);
        pack2(a01.x, a01.y, hi.z, lo.z);
        pack2(a11.x, a11.y, hi.w, lo.w);
        sA[buf][(wid * 2 + 0) * 32 + lane] = hi;
        sA[buf][(wid * 2 + 1) * 32 + lane] = lo;
        uint2* sbp = (uint2*)&sB[buf][0];
        float e0 = __expf(b0[0] - mx0) * iv0, e1 = __expf(b0[1] - mx0) * iv0;
        float e2 = __expf(b0[2] - mx0) * iv0, e3 = __expf(b0[3] - mx0) * iv0;
        unsigned h0, l0, h1, l1;
        pack2(e0, e1, h0, l0); pack2(e2, e3, h1, l1);
        sbp[((wid * 2 + 0) * 2 + 0) * 32 + lane] = make_uint2(h0, h1);
        sbp[((wid * 2 + 0) * 2 + 1) * 32 + lane] = make_uint2(l0, l1);
        e0 = __expf(b1[0] - mx1) * iv1; e1 = __expf(b1[1] - mx1) * iv1;
        e2 = __expf(b1[2] - mx1) * iv1; e3 = __expf(b1[3] - mx1) * iv1;
        pack2(e0, e1, h0, l0); pack2(e2, e3, h1, l1);
        sbp[((wid * 2 + 1) * 2 + 0) * 32 + lane] = make_uint2(h0, h1);
        sbp[((wid * 2 + 1) * 2 + 1) * 32 + lane] = make_uint2(l0, l1);
    };

    gload(0); sstore(0);
    __syncthreads();

    float acc[4][4][4] = {};
    for (int ks = 0; ks < 16; ks++) {
        int cur = ks & 1, nxt = cur ^ 1;
        bool more = ks + 1 < 16;
        if (more) gload(ks + 1);
        frag_mma(&sA[cur][0], (const uint2*)&sB[cur][0], wm, wn, lane, acc);
        if (more) { sstore(nxt); __syncthreads(); }
    }

    // acc rows = e (g-pattern), cols = d (tc-pairs) → B-frag (k=d, n=e), in-lane
    uint2* dst = g_ctxp + (size_t)sb * 8192;
    #pragma unroll
    for (int i = 0; i < 4; i++) {
        int nf0 = wm * 8 + 2 * i;
        #pragma unroll
        for (int jp = 0; jp < 2; jp++) {
            int ks = wn * 2 + jp;
            store_bfrag(dst, (size_t)ks * 1024, nf0, lane, acc[i][2 * jp], acc[i][2 * jp + 1]);
        }
    }
}

// ---------------------------------------------------------------------------
// applyT: attT[t][e] = sum_d q[d,t] * ctxT[e,d]
//   A = q^T staged (M=t), B = prepacked ctx frags. Epilogue writes gB_att
//   packed B-frags (k=f=h*128+e, n=t) for the out GEMM — in-lane mapping.
// ---------------------------------------------------------------------------
__global__ __launch_bounds__(256, 1)
void k_applyT_mma() {
    __shared__ uint4 sA[2][512];
    __shared__ uint4 sB[2][512];
    int sb = blockIdx.z, s = sb >> 2, h = sb & 3;
    int mband = blockIdx.x;
    int tid = threadIdx.x, wid = tid >> 5, lane = tid & 31;
    int wm = wid >> 2, wn = wid & 3, g = lane >> 2, tc = (lane & 3) * 2;

    const float* q = g_qkv + (size_t)s * OC3 * T_ + (size_t)(h * C_) * T_;
    const uint4* Bch = (const uint4*)g_ctxp + (size_t)sb * 4096;
    int m = mband * 128 + wid * 16 + g;    // t index of this warp's A frag

    float av[8];
    uint4 nb0, nb1;
    auto gloadA = [&](int ks) {
        int k0 = ks * 16 + tc;
        av[0] = q[(size_t)(k0 + 0) * T_ + m];     av[1] = q[(size_t)(k0 + 1) * T_ + m];
        av[2] = q[(size_t)(k0 + 0) * T_ + m + 8]; av[3] = q[(size_t)(k0 + 1) * T_ + m + 8];
        av[4] = q[(size_t)(k0 + 8) * T_ + m];     av[5] = q[(size_t)(k0 + 9) * T_ + m];
        av[6] = q[(size_t)(k0 + 8) * T_ + m + 8]; av[7] = q[(size_t)(k0 + 9) * T_ + m + 8];
    };
    auto gloadB = [&](int ks) {
        nb0 = Bch[(size_t)ks * 512 + tid];
        nb1 = Bch[(size_t)ks * 512 + tid + 256];
    };
    auto sstore = [&](int buf) {
        uint4 hi, lo;
        pack2(av[0], av[1], hi.x, lo.x);
        pack2(av[2], av[3], hi.y, lo.y);
        pack2(av[4], av[5], hi.z, lo.z);
        pack2(av[6], av[7], hi.w, lo.w);
        sA[buf][(wid * 2 + 0) * 32 + lane] = hi;
        sA[buf][(wid * 2 + 1) * 32 + lane] = lo;
        sB[buf][tid] = nb0;
        sB[buf][tid + 256] = nb1;
    };

    gloadA(0); gloadB(0); sstore(0);
    __syncthreads();

    float acc[4][4][4] = {};
    for (int ks = 0; ks < 8; ks++) {
        int cur = ks & 1, nxt = cur ^ 1;
        bool more = ks + 1 < 8;
        if (more) { gloadA(ks + 1); gloadB(ks + 1); }
        frag_mma(&sA[cur][0], (const uint2*)&sB[cur][0], wm, wn, lane, acc);
        if (more) { sstore(nxt); __syncthreads(); }
    }

    // acc rows = t (g-pattern), cols = e (tc-pairs) → gB_att B-frag (k=f, n=t)
    uint2* dst = gB_att + (size_t)s * BATT_SLICE;
    #pragma unroll
    for (int i = 0; i < 4; i++) {
        int nf0 = wm * 8 + 2 * i;
        #pragma unroll
        for (int jp = 0; jp < 2; jp++) {
            int ks = h * 8 + wn * 2 + jp;
            size_t cb = ((size_t)mband * 32 + ks) * 1024;
            store_bfrag(dst, cb, nf0, lane, acc[i][2 * jp], acc[i][2 * jp + 1]);
        }
    }
}

// ---------------------------------------------------------------------------
// temb
// ---------------------------------------------------------------------------
__global__ void k_temb(const float* __restrict__ time_in,
                       const float* __restrict__ w_time,
                       const float* __restrict__ b_time) {
    int s = blockIdx.x;
    int t = threadIdx.x;
    __shared__ float m[256];
    float v = time_in[(size_t)s * 256 + t];
    float sp = (v > 20.f) ? v : log1pf(__expf(v));
    m[t] = v * tanhf(sp);
    __syncthreads();

    int warp = t >> 5, lane = t & 31;
    for (int o = warp; o < OC3; o += 8) {
        const float* w = w_time + (size_t)o * 256;
        float acc = 0.f;
        #pragma unroll 4
        for (int e = lane; e < 256; e += 32) acc += m[e] * w[e];
        #pragma unroll
        for (int off = 16; off; off >>= 1) acc += __shfl_down_sync(0xffffffffu, acc, off);
        if (lane == 0) g_temb[(size_t)s * OC3 + o] = acc + b_time[o];
    }
}

// ---------------------------------------------------------------------------
extern "C" void kernel_launch(void* const* d_in, const int* in_sizes, int n_in,
                              void* d_out, int out_size) {
    (void)in_sizes; (void)n_in; (void)out_size;
    const float* x       = (const float*)d_in[0];
    const float* time_in = (const float*)d_in[1];
    const float* w_qkv   = (const float*)d_in[2];
    const float* w_time  = (const float*)d_in[3];
    const float* b_time  = (const float*)d_in[4];
    const float* w_out   = (const float*)d_in[5];
    const float* b_out   = (const float*)d_in[6];
    float* out = (float*)d_out;

    uint4* pA_qkv; cudaGetSymbolAddress((void**)&pA_qkv, gA_qkv);
    uint4* pA_out; cudaGetSymbolAddress((void**)&pA_out, gA_out);
    uint2* pB_x;   cudaGetSymbolAddress((void**)&pB_x,   gB_x);
    uint2* pB_att; cudaGetSymbolAddress((void**)&pB_att, gB_att);

    k_temb<<<S_, 256>>>(time_in, w_time, b_time);

    conv_A<<<192, 256>>>(w_qkv, F_, 16, pA_qkv);
    conv_A<<<64, 256>>>(w_out, HID, 32, pA_out);
    conv_Bd<<<dim3(64, S_), 256>>>(x, T_, 16, (size_t)F_ * T_, pB_x, BX_SLICE);

    k_qkv_mma<<<dim3(2, 12, S_), 256>>>(pA_qkv, pB_x);

    k_kstats<<<(S_ * HID) / 8, 256>>>();
    k_ctx_mma<<<S_ * HEADS, 256>>>();
    k_applyT_mma<<<dim3(2, 1, S_ * HEADS), 256>>>();

    k_out_mma<<<dim3(2, 2, S_), 256>>>(pA_out, pB_att, b_out, out);
}

// round 6
// speedup vs baseline: 4.4913x; 1.4986x over previous
#include <cuda_runtime.h>
#include <cuda_fp16.h>
#include <math.h>

// Problem constants
#define B_   64
#define A_   8
#define S_   512
#define F_   256
#define T_   256
#define HID  512
#define OC3  1536
#define HEADS 4
#define C_   128
#define QKROWS 1024      // q+k rows kept in fp32 per slice

// ---------------------------------------------------------------------------
// Scratch
// ---------------------------------------------------------------------------
__device__ float g_temb[(size_t)S_ * OC3];
__device__ float g_qkv [(size_t)S_ * QKROWS * T_];              // 537 MB (q+k fp32)
__device__ float g_kmax[(size_t)S_ * HID];
__device__ float g_kinv[(size_t)S_ * HID];
__device__ uint4 g_vp  [(size_t)S_ * HEADS * 4096];             // v packed A-frags (hi)
__device__ uint2 g_ctxp[(size_t)S_ * HEADS * 8192];             // ctx packed B-frags

// prepacked operands
__device__ uint4 gA_qkv[(size_t)12 * 16 * 8 * 32];              // hi only
__device__ uint4 gA_out[(size_t)2 * 32 * 8 * 32];               // hi only
__device__ uint2 gB_x  [(size_t)S_ * 2 * 16 * 16 * 2 * 32];     // hi+lo
__device__ uint2 gB_att[(size_t)S_ * 2 * 32 * 16 * 2 * 32];     // hi+lo

#define BX_SLICE   ((size_t)2 * 16 * 16 * 2 * 32)
#define BATT_SLICE ((size_t)2 * 32 * 16 * 2 * 32)

// ---------------------------------------------------------------------------
// helpers (fp16 split)
// ---------------------------------------------------------------------------
__device__ __forceinline__ unsigned hpack(float x, float y) {
    __half2 h = __floats2half2_rn(x, y);
    return *reinterpret_cast<unsigned*>(&h);
}
__device__ __forceinline__ void hsplit(float v, float& hi, float& lo) {
    __half h = __float2half_rn(v);
    hi = __half2float(h);
    lo = v - hi;
}
__device__ __forceinline__ void hpack2(float x, float y, unsigned& hi, unsigned& lo) {
    float hx, lx, hy, ly;
    hsplit(x, hx, lx); hsplit(y, hy, ly);
    hi = hpack(hx, hy); lo = hpack(lx, ly);
}
__device__ __forceinline__ void mma_f16(float* c, const uint4& a, const uint2& b) {
    asm volatile(
        "mma.sync.aligned.m16n8k16.row.col.f32.f16.f16.f32 "
        "{%0,%1,%2,%3}, {%4,%5,%6,%7}, {%8,%9}, {%0,%1,%2,%3};\n"
        : "+f"(c[0]), "+f"(c[1]), "+f"(c[2]), "+f"(c[3])
        : "r"(a.x), "r"(a.y), "r"(a.z), "r"(a.w), "r"(b.x), "r"(b.y));
}

// cp.async
__device__ __forceinline__ void cp16(uint4* smem, const uint4* gmem) {
    unsigned sa = (unsigned)__cvta_generic_to_shared(smem);
    asm volatile("cp.async.cg.shared.global [%0], [%1], 16;\n" :: "r"(sa), "l"(gmem));
}
__device__ __forceinline__ void cp_commit() { asm volatile("cp.async.commit_group;\n" ::); }
__device__ __forceinline__ void cp_wait1()  { asm volatile("cp.async.wait_group 1;\n" ::); }
__device__ __forceinline__ void cp_wait0()  { asm volatile("cp.async.wait_group 0;\n" ::); }

// 2-pass frag mma: A hi-only (4 uint4), B hi+lo (8 uint2) — 32 mma per call
__device__ __forceinline__ void frag_mma2(const uint4* sa, const uint2* sbp,
                                          int wm, int wn, int lane, float acc[4][4][4]) {
    uint4 a[4]; uint2 b[4][2];
    #pragma unroll
    for (int i = 0; i < 4; i++) a[i] = sa[(wm * 4 + i) * 32 + lane];
    #pragma unroll
    for (int j = 0; j < 4; j++) {
        int nf = wn * 4 + j;
        b[j][0] = sbp[(nf * 2 + 0) * 32 + lane];
        b[j][1] = sbp[(nf * 2 + 1) * 32 + lane];
    }
    #pragma unroll
    for (int i = 0; i < 4; i++)
        #pragma unroll
        for (int j = 0; j < 4; j++) {
            mma_f16(acc[i][j], a[i], b[j][0]);
            mma_f16(acc[i][j], a[i], b[j][1]);
        }
}

// store a 16(row)x16(k-pairs) accumulator block as hi/lo B-frags
__device__ __forceinline__ void store_hfrag(uint2* dst, size_t cb, int nf0, int lane,
                                            const float* a0, const float* a1) {
    unsigned h00,l00,h01,l01,h10,l10,h11,l11;
    hpack2(a0[0], a0[1], h00, l00); hpack2(a1[0], a1[1], h01, l01);
    hpack2(a0[2], a0[3], h10, l10); hpack2(a1[2], a1[3], h11, l11);
    dst[cb + (size_t)(nf0 * 2 + 0) * 32 + lane] = make_uint2(h00, h01);
    dst[cb + (size_t)(nf0 * 2 + 1) * 32 + lane] = make_uint2(l00, l01);
    dst[cb + (size_t)((nf0 + 1) * 2 + 0) * 32 + lane] = make_uint2(h10, h11);
    dst[cb + (size_t)((nf0 + 1) * 2 + 1) * 32 + lane] = make_uint2(l10, l11);
}

// ---------------------------------------------------------------------------
// conv_A: fp32 [M,K] row-major -> A-frags, hi plane only
// ---------------------------------------------------------------------------
__global__ void conv_A(const float* __restrict__ src, int lda, int Ksteps,
                       uint4* __restrict__ dst) {
    int wg   = blockIdx.x * 8 + (threadIdx.x >> 5);
    int lane = threadIdx.x & 31;
    int mf   = wg & 7;
    int ks   = (wg >> 3) % Ksteps;
    int band = wg / (8 * Ksteps);
    int g = lane >> 2, tc = (lane & 3) * 2;

    const float* p = src + (size_t)(band * 128 + mf * 16 + g) * lda + ks * 16 + tc;
    float2 p00 = *(const float2*)p;
    float2 p01 = *(const float2*)(p + 8);
    float2 p10 = *(const float2*)(p + (size_t)8 * lda);
    float2 p11 = *(const float2*)(p + (size_t)8 * lda + 8);

    uint4 hi;
    hi.x = hpack(__half2float(__float2half_rn(p00.x)), __half2float(__float2half_rn(p00.y)));
    hi.x = hpack(p00.x, p00.y);   // rn pack directly
    hi.y = hpack(p10.x, p10.y);
    hi.z = hpack(p01.x, p01.y);
    hi.w = hpack(p11.x, p11.y);

    dst[(((size_t)band * Ksteps + ks) * 8 + mf) * 32 + lane] = hi;
}

// ---------------------------------------------------------------------------
// conv_Bd: fp32 [K,N] row-major (per slice) -> B-frags hi+lo
// ---------------------------------------------------------------------------
__global__ void conv_Bd(const float* __restrict__ srcbase, int ldb, int Ksteps,
                        size_t src_slice_stride,
                        uint2* __restrict__ dstbase, size_t dst_slice_stride) {
    int s = blockIdx.y;
    const float* src = srcbase + (size_t)s * src_slice_stride;
    uint2* dst = dstbase + (size_t)s * dst_slice_stride;

    int wg   = blockIdx.x * 8 + (threadIdx.x >> 5);
    int lane = threadIdx.x & 31;
    int nf   = wg & 15;
    int ks   = (wg >> 4) % Ksteps;
    int band = wg / (16 * Ksteps);
    int g = lane >> 2, tc = (lane & 3) * 2;

    int n = band * 128 + nf * 8 + g;
    const float* p = src + (size_t)(ks * 16 + tc) * ldb + n;
    float v0 = p[0];
    float v1 = p[(size_t)ldb];
    float v2 = p[(size_t)8 * ldb];
    float v3 = p[(size_t)9 * ldb];

    unsigned h0, l0, h1, l1;
    hpack2(v0, v1, h0, l0);
    hpack2(v2, v3, h1, l1);

    size_t base = ((((size_t)band * Ksteps + ks) * 16 + nf) * 2) * 32 + lane;
    dst[base]      = make_uint2(h0, h1);
    dst[base + 32] = make_uint2(l0, l1);
}

// ---------------------------------------------------------------------------
// mma tile (prepacked, A hi-only), 3-stage cp.async pipeline
// A: 256 uint4 / kstep, B: 512 uint4 / kstep
// ---------------------------------------------------------------------------
__device__ __forceinline__ void mma_tile3(const uint4* __restrict__ Ach,
                                          const uint4* __restrict__ Bch,
                                          int Ksteps, float acc[4][4][4]) {
    __shared__ uint4 sA[3][256];
    __shared__ uint4 sB[3][512];
    int tid = threadIdx.x, wid = tid >> 5, lane = tid & 31;
    int wm = wid >> 2, wn = wid & 3;

    auto issue = [&](int ks) {
        int st = ks % 3;
        const uint4* A = Ach + (size_t)ks * 256;
        const uint4* B = Bch + (size_t)ks * 512;
        cp16(&sA[st][tid], A + tid);
        cp16(&sB[st][tid], B + tid); cp16(&sB[st][tid + 256], B + tid + 256);
        cp_commit();
    };
    issue(0);
    issue(1);

    for (int ks = 0; ks < Ksteps; ks++) {
        if (ks + 1 < Ksteps) cp_wait1(); else cp_wait0();
        __syncthreads();
        if (ks + 2 < Ksteps) issue(ks + 2);
        frag_mma2(&sA[ks % 3][0], (const uint2*)&sB[ks % 3][0], wm, wn, lane, acc);
    }
}

// ---------------------------------------------------------------------------
// qkv GEMM: q,k rows -> fp32 g_qkv; v rows -> packed A-frags g_vp (+temb)
// ---------------------------------------------------------------------------
__global__ __launch_bounds__(256, 2)
void k_qkv_mma(const uint4* __restrict__ Ap, const uint2* __restrict__ Bp) {
    int s = blockIdx.z, bandA = blockIdx.y, bandB = blockIdx.x;
    const uint4* Ach = Ap + (size_t)bandA * 16 * 256;
    const uint4* Bch = (const uint4*)(Bp + (size_t)s * BX_SLICE) + (size_t)bandB * 16 * 512;

    float acc[4][4][4] = {};
    mma_tile3(Ach, Bch, 16, acc);

    int tid = threadIdx.x, wid = tid >> 5, lane = tid & 31;
    int wm = wid >> 2, wn = wid & 3;
    int g = lane >> 2, tc = (lane & 3) * 2;
    const float* te = g_temb + (size_t)s * OC3;

    if (bandA < 8) {
        float* Co = g_qkv + (size_t)s * QKROWS * T_;
        #pragma unroll
        for (int i = 0; i < 4; i++) {
            int m = bandA * 128 + wm * 64 + i * 16 + g;
            float t0 = te[m], t1 = te[m + 8];
            #pragma unroll
            for (int j = 0; j < 4; j++) {
                int n = bandB * 128 + wn * 32 + j * 8 + tc;
                *(float2*)(Co + (size_t)m * T_ + n) =
                    make_float2(acc[i][j][0] + t0, acc[i][j][1] + t0);
                *(float2*)(Co + (size_t)(m + 8) * T_ + n) =
                    make_float2(acc[i][j][2] + t1, acc[i][j][3] + t1);
            }
        }
    } else {
        int h = bandA - 8;
        uint4* dst = g_vp + ((size_t)(s * HEADS + h)) * 4096;
        #pragma unroll
        for (int i = 0; i < 4; i++) {
            int mf = wm * 4 + i;
            int m = bandA * 128 + mf * 16 + g;
            float t0 = te[m], t1 = te[m + 8];
            #pragma unroll
            for (int jp = 0; jp < 2; jp++) {
                int ks = bandB * 8 + wn * 2 + jp;
                uint4 hi;
                hi.x = hpack(acc[i][2*jp][0] + t0, acc[i][2*jp][1] + t0);
                hi.y = hpack(acc[i][2*jp][2] + t1, acc[i][2*jp][3] + t1);
                hi.z = hpack(acc[i][2*jp+1][0] + t0, acc[i][2*jp+1][1] + t0);
                hi.w = hpack(acc[i][2*jp+1][2] + t1, acc[i][2*jp+1][3] + t1);
                dst[(size_t)ks * 256 + mf * 32 + lane] = hi;
            }
        }
    }
}

// ---------------------------------------------------------------------------
// out GEMM (prepacked A hi + prepacked B hi/lo)
// ---------------------------------------------------------------------------
__global__ __launch_bounds__(256, 2)
void k_out_mma(const uint4* __restrict__ Ap, const uint2* __restrict__ Bp,
               const float* __restrict__ bias, float* __restrict__ out) {
    int s = blockIdx.z, bandA = blockIdx.y, bandB = blockIdx.x;
    const uint4* Ach = Ap + (size_t)bandA * 32 * 256;
    const uint4* Bch = (const uint4*)(Bp + (size_t)s * BATT_SLICE) + (size_t)bandB * 32 * 512;

    float acc[4][4][4] = {};
    mma_tile3(Ach, Bch, 32, acc);

    int tid = threadIdx.x, wid = tid >> 5, lane = tid & 31;
    int wm = wid >> 2, wn = wid & 3;
    int g = lane >> 2, tc = (lane & 3) * 2;
    float* Co = out + (size_t)s * 256 * T_;

    #pragma unroll
    for (int i = 0; i < 4; i++) {
        int m = bandA * 128 + wm * 64 + i * 16 + g;
        float t0 = bias[m], t1 = bias[m + 8];
        #pragma unroll
        for (int j = 0; j < 4; j++) {
            int n = bandB * 128 + wn * 32 + j * 8 + tc;
            *(float2*)(Co + (size_t)m * T_ + n) =
                make_float2(acc[i][j][0] + t0, acc[i][j][1] + t0);
            *(float2*)(Co + (size_t)(m + 8) * T_ + n) =
                make_float2(acc[i][j][2] + t1, acc[i][j][3] + t1);
        }
    }
}

// ---------------------------------------------------------------------------
// k stats
// ---------------------------------------------------------------------------
__global__ void k_kstats() {
    int row  = blockIdx.x * 8 + (threadIdx.x >> 5);
    int lane = threadIdx.x & 31;
    int s = row >> 9, r = row & 511;
    const float* p = g_qkv + (size_t)s * QKROWS * T_ + (size_t)(HID + r) * T_ + lane * 8;

    float4 v0 = *(const float4*)p;
    float4 v1 = *(const float4*)(p + 4);
    float mx = fmaxf(fmaxf(fmaxf(v0.x, v0.y), fmaxf(v0.z, v0.w)),
                     fmaxf(fmaxf(v1.x, v1.y), fmaxf(v1.z, v1.w)));
    #pragma unroll
    for (int off = 16; off; off >>= 1)
        mx = fmaxf(mx, __shfl_xor_sync(0xffffffffu, mx, off));

    float sm = __expf(v0.x - mx) + __expf(v0.y - mx) + __expf(v0.z - mx) + __expf(v0.w - mx)
             + __expf(v1.x - mx) + __expf(v1.y - mx) + __expf(v1.z - mx) + __expf(v1.w - mx);
    #pragma unroll
    for (int off = 16; off; off >>= 1)
        sm += __shfl_xor_sync(0xffffffffu, sm, off);

    if (lane == 0) {
        g_kmax[row] = mx;
        g_kinv[row] = 1.f / sm;
    }
}

// ---------------------------------------------------------------------------
// ctx: ctxT[e][d] = sum_t v[e,t]*softmax(k)[d,t]
// A = prepacked v frags (cp.async); B = staged softmax(k) hi/lo
// epilogue -> g_ctxp packed B-frags
// ---------------------------------------------------------------------------
__global__ __launch_bounds__(256, 2)
void k_ctx_mma() {
    __shared__ uint4 sA[2][256];
    __shared__ uint4 sB[2][512];
    int sb = blockIdx.x, s = sb >> 2, h = sb & 3;
    int tid = threadIdx.x, wid = tid >> 5, lane = tid & 31;
    int wm = wid >> 2, wn = wid & 3, g = lane >> 2, tc = (lane & 3) * 2;

    const uint4* Vch = g_vp + (size_t)sb * 4096;
    const float* kraw = g_qkv + (size_t)s * QKROWS * T_ + (size_t)(HID + h * C_) * T_;
    int rb = s * HID + h * C_;
    float mx0 = g_kmax[rb + wid * 16 + g],     iv0 = g_kinv[rb + wid * 16 + g];
    float mx1 = g_kmax[rb + wid * 16 + 8 + g], iv1 = g_kinv[rb + wid * 16 + 8 + g];

    const float* Bp0 = kraw + (size_t)(wid * 16 + g) * T_ + tc;
    const float* Bp1 = kraw + (size_t)(wid * 16 + 8 + g) * T_ + tc;

    float b0[4], b1[4];
    auto gloadB = [&](int ks) {
        const float* q0 = Bp0 + ks * 16;
        b0[0] = q0[0]; b0[1] = q0[1]; b0[2] = q0[8]; b0[3] = q0[9];
        const float* q1 = Bp1 + ks * 16;
        b1[0] = q1[0]; b1[1] = q1[1]; b1[2] = q1[8]; b1[3] = q1[9];
    };
    auto sstoreB = [&](int buf) {
        uint2* sbp = (uint2*)&sB[buf][0];
        float e0 = __expf(b0[0] - mx0) * iv0, e1 = __expf(b0[1] - mx0) * iv0;
        float e2 = __expf(b0[2] - mx0) * iv0, e3 = __expf(b0[3] - mx0) * iv0;
        unsigned h0, l0, h1, l1;
        hpack2(e0, e1, h0, l0); hpack2(e2, e3, h1, l1);
        sbp[((wid * 2 + 0) * 2 + 0) * 32 + lane] = make_uint2(h0, h1);
        sbp[((wid * 2 + 0) * 2 + 1) * 32 + lane] = make_uint2(l0, l1);
        e0 = __expf(b1[0] - mx1) * iv1; e1 = __expf(b1[1] - mx1) * iv1;
        e2 = __expf(b1[2] - mx1) * iv1; e3 = __expf(b1[3] - mx1) * iv1;
        hpack2(e0, e1, h0, l0); hpack2(e2, e3, h1, l1);
        sbp[((wid * 2 + 1) * 2 + 0) * 32 + lane] = make_uint2(h0, h1);
        sbp[((wid * 2 + 1) * 2 + 1) * 32 + lane] = make_uint2(l0, l1);
    };

    cp16(&sA[0][tid], Vch + tid); cp_commit();
    gloadB(0); sstoreB(0);
    cp_wait0();
    __syncthreads();

    float acc[4][4][4] = {};
    for (int ks = 0; ks < 16; ks++) {
        int cur = ks & 1, nxt = cur ^ 1;
        bool more = ks + 1 < 16;
        if (more) {
            cp16(&sA[nxt][tid], Vch + (size_t)(ks + 1) * 256 + tid); cp_commit();
            gloadB(ks + 1);
        }
        frag_mma2(&sA[cur][0], (const uint2*)&sB[cur][0], wm, wn, lane, acc);
        if (more) { sstoreB(nxt); cp_wait0(); __syncthreads(); }
    }

    uint2* dst = g_ctxp + (size_t)sb * 8192;
    #pragma unroll
    for (int i = 0; i < 4; i++) {
        int nf0 = wm * 8 + 2 * i;
        #pragma unroll
        for (int jp = 0; jp < 2; jp++) {
            int ks = wn * 2 + jp;
            store_hfrag(dst, (size_t)ks * 1024, nf0, lane, acc[i][2 * jp], acc[i][2 * jp + 1]);
        }
    }
}

// ---------------------------------------------------------------------------
// applyT: attT[t][e] = sum_d q[d,t]*ctxT[e,d]
// A = q^T staged hi-only; B = prepacked ctx frags (cp.async)
// epilogue -> gB_att packed B-frags
// ---------------------------------------------------------------------------
__global__ __launch_bounds__(256, 2)
void k_applyT_mma() {
    __shared__ uint4 sA[2][256];
    __shared__ uint4 sB[2][512];
    int sb = blockIdx.z, s = sb >> 2, h = sb & 3;
    int mband = blockIdx.x;
    int tid = threadIdx.x, wid = tid >> 5, lane = tid & 31;
    int wm = wid >> 2, wn = wid & 3, g = lane >> 2, tc = (lane & 3) * 2;

    const float* q = g_qkv + (size_t)s * QKROWS * T_ + (size_t)(h * C_) * T_;
    const uint4* Bch = (const uint4*)g_ctxp + (size_t)sb * 4096;
    int m = mband * 128 + wid * 16 + g;

    float av[8];
    auto gloadA = [&](int ks) {
        int k0 = ks * 16 + tc;
        av[0] = q[(size_t)(k0 + 0) * T_ + m];     av[1] = q[(size_t)(k0 + 1) * T_ + m];
        av[2] = q[(size_t)(k0 + 0) * T_ + m + 8]; av[3] = q[(size_t)(k0 + 1) * T_ + m + 8];
        av[4] = q[(size_t)(k0 + 8) * T_ + m];     av[5] = q[(size_t)(k0 + 9) * T_ + m];
        av[6] = q[(size_t)(k0 + 8) * T_ + m + 8]; av[7] = q[(size_t)(k0 + 9) * T_ + m + 8];
    };
    auto sstoreA = [&](int buf) {
        uint4 hi;
        hi.x = hpack(av[0], av[1]);
        hi.y = hpack(av[2], av[3]);
        hi.z = hpack(av[4], av[5]);
        hi.w = hpack(av[6], av[7]);
        sA[buf][wid * 32 + lane] = hi;
    };

    cp16(&sB[0][tid], Bch + tid); cp16(&sB[0][tid + 256], Bch + tid + 256); cp_commit();
    gloadA(0); sstoreA(0);
    cp_wait0();
    __syncthreads();

    float acc[4][4][4] = {};
    for (int ks = 0; ks < 8; ks++) {
        int cur = ks & 1, nxt = cur ^ 1;
        bool more = ks + 1 < 8;
        if (more) {
            const uint4* B = Bch + (size_t)(ks + 1) * 512;
            cp16(&sB[nxt][tid], B + tid); cp16(&sB[nxt][tid + 256], B + tid + 256); cp_commit();
            gloadA(ks + 1);
        }
        frag_mma2(&sA[cur][0], (const uint2*)&sB[cur][0], wm, wn, lane, acc);
        if (more) { sstoreA(nxt); cp_wait0(); __syncthreads(); }
    }

    uint2* dst = gB_att + (size_t)s * BATT_SLICE;
    #pragma unroll
    for (int i = 0; i < 4; i++) {
        int nf0 = wm * 8 + 2 * i;
        #pragma unroll
        for (int jp = 0; jp < 2; jp++) {
            int ks = h * 8 + wn * 2 + jp;
            size_t cb = ((size_t)mband * 32 + ks) * 1024;
            store_hfrag(dst, cb, nf0, lane, acc[i][2 * jp], acc[i][2 * jp + 1]);
        }
    }
}

// ---------------------------------------------------------------------------
// temb
// ---------------------------------------------------------------------------
__global__ void k_temb(const float* __restrict__ time_in,
                       const float* __restrict__ w_time,
                       const float* __restrict__ b_time) {
    int s = blockIdx.x;
    int t = threadIdx.x;
    __shared__ float m[256];
    float v = time_in[(size_t)s * 256 + t];
    float sp = (v > 20.f) ? v : log1pf(__expf(v));
    m[t] = v * tanhf(sp);
    __syncthreads();

    int warp = t >> 5, lane = t & 31;
    for (int o = warp; o < OC3; o += 8) {
        const float* w = w_time + (size_t)o * 256;
        float acc = 0.f;
        #pragma unroll 4
        for (int e = lane; e < 256; e += 32) acc += m[e] * w[e];
        #pragma unroll
        for (int off = 16; off; off >>= 1) acc += __shfl_down_sync(0xffffffffu, acc, off);
        if (lane == 0) g_temb[(size_t)s * OC3 + o] = acc + b_time[o];
    }
}

// ---------------------------------------------------------------------------
extern "C" void kernel_launch(void* const* d_in, const int* in_sizes, int n_in,
                              void* d_out, int out_size) {
    (void)in_sizes; (void)n_in; (void)out_size;
    const float* x       = (const float*)d_in[0];
    const float* time_in = (const float*)d_in[1];
    const float* w_qkv   = (const float*)d_in[2];
    const float* w_time  = (const float*)d_in[3];
    const float* b_time  = (const float*)d_in[4];
    const float* w_out   = (const float*)d_in[5];
    const float* b_out   = (const float*)d_in[6];
    float* out = (float*)d_out;

    uint4* pA_qkv; cudaGetSymbolAddress((void**)&pA_qkv, gA_qkv);
    uint4* pA_out; cudaGetSymbolAddress((void**)&pA_out, gA_out);
    uint2* pB_x;   cudaGetSymbolAddress((void**)&pB_x,   gB_x);
    uint2* pB_att; cudaGetSymbolAddress((void**)&pB_att, gB_att);

    k_temb<<<S_, 256>>>(time_in, w_time, b_time);

    conv_A<<<192, 256>>>(w_qkv, F_, 16, pA_qkv);
    conv_A<<<64, 256>>>(w_out, HID, 32, pA_out);
    conv_Bd<<<dim3(64, S_), 256>>>(x, T_, 16, (size_t)F_ * T_, pB_x, BX_SLICE);

    k_qkv_mma<<<dim3(2, 12, S_), 256>>>(pA_qkv, pB_x);

    k_kstats<<<(S_ * HID) / 8, 256>>>();
    k_ctx_mma<<<S_ * HEADS, 256>>>();
    k_applyT_mma<<<dim3(2, 1, S_ * HEADS), 256>>>();

    k_out_mma<<<dim3(2, 2, S_), 256>>>(pA_out, pB_att, b_out, out);
}

// round 7
// speedup vs baseline: 4.5848x; 1.0208x over previous
#include <cuda_runtime.h>
#include <cuda_fp16.h>
#include <math.h>

// Problem constants
#define B_   64
#define A_   8
#define S_   512
#define F_   256
#define T_   256
#define HID  512
#define OC3  1536
#define HEADS 4
#define C_   128

// ---------------------------------------------------------------------------
// Scratch
// ---------------------------------------------------------------------------
__device__ float  g_temb[(size_t)S_ * OC3];
__device__ __half g_q16 [(size_t)S_ * HID * T_];                 // q fp16 [s][d][t]
__device__ uint4  g_vp  [(size_t)S_ * HEADS * 4096];             // v packed A-frags (hi)
__device__ uint2  g_kp  [(size_t)S_ * HEADS * 16384];            // softmax(k) packed B-frags hi+lo
__device__ uint2  g_ctxp[(size_t)S_ * HEADS * 8192];             // ctx packed B-frags hi+lo

// prepacked operands
__device__ uint4 gA_qkv[(size_t)24 * 16 * 4 * 32];               // weights hi, [band64][ks][mf4][32]
__device__ uint4 gA_out[(size_t)4 * 32 * 4 * 32];
__device__ uint2 gB_x  [(size_t)S_ * 16 * 32 * 2 * 32];          // [s][ks][nf32][plane][32]
__device__ uint2 gB_att[(size_t)S_ * 32 * 32 * 2 * 32];          // written by applyT

#define BX_SLICE4   ((size_t)16 * 1024)    // uint4 per slice (x frags)
#define BATT_SLICE4 ((size_t)32 * 1024)    // uint4 per slice (att frags)
#define BATT_SLICE2 ((size_t)32 * 2048)    // uint2 per slice

// ---------------------------------------------------------------------------
// helpers (fp16 split)
// ---------------------------------------------------------------------------
__device__ __forceinline__ unsigned hpack(float x, float y) {
    __half2 h = __floats2half2_rn(x, y);
    return *reinterpret_cast<unsigned*>(&h);
}
__device__ __forceinline__ unsigned hpack_hh(__half a, __half b) {
    __half2 h = __halves2half2(a, b);
    return *reinterpret_cast<unsigned*>(&h);
}
__device__ __forceinline__ void hsplit(float v, float& hi, float& lo) {
    __half h = __float2half_rn(v);
    hi = __half2float(h);
    lo = v - hi;
}
__device__ __forceinline__ void hpack2(float x, float y, unsigned& hi, unsigned& lo) {
    float hx, lx, hy, ly;
    hsplit(x, hx, lx); hsplit(y, hy, ly);
    hi = hpack(hx, hy); lo = hpack(lx, ly);
}
__device__ __forceinline__ void mma_f16(float* c, const uint4& a, const uint2& b) {
    asm volatile(
        "mma.sync.aligned.m16n8k16.row.col.f32.f16.f16.f32 "
        "{%0,%1,%2,%3}, {%4,%5,%6,%7}, {%8,%9}, {%0,%1,%2,%3};\n"
        : "+f"(c[0]), "+f"(c[1]), "+f"(c[2]), "+f"(c[3])
        : "r"(a.x), "r"(a.y), "r"(a.z), "r"(a.w), "r"(b.x), "r"(b.y));
}

// cp.async
__device__ __forceinline__ void cp16(uint4* smem, const uint4* gmem) {
    unsigned sa = (unsigned)__cvta_generic_to_shared(smem);
    asm volatile("cp.async.cg.shared.global [%0], [%1], 16;\n" :: "r"(sa), "l"(gmem));
}
__device__ __forceinline__ void cp_commit() { asm volatile("cp.async.commit_group;\n" ::); }
__device__ __forceinline__ void cp_wait1()  { asm volatile("cp.async.wait_group 1;\n" ::); }
__device__ __forceinline__ void cp_wait0()  { asm volatile("cp.async.wait_group 0;\n" ::); }

// store a 16(row)x16(k-pairs) accumulator block as hi/lo B-frags
__device__ __forceinline__ void store_hfrag(uint2* dst, size_t cb, int nf0, int lane,
                                            const float* a0, const float* a1) {
    unsigned h00,l00,h01,l01,h10,l10,h11,l11;
    hpack2(a0[0], a0[1], h00, l00); hpack2(a1[0], a1[1], h01, l01);
    hpack2(a0[2], a0[3], h10, l10); hpack2(a1[2], a1[3], h11, l11);
    dst[cb + (size_t)(nf0 * 2 + 0) * 32 + lane] = make_uint2(h00, h01);
    dst[cb + (size_t)(nf0 * 2 + 1) * 32 + lane] = make_uint2(l00, l01);
    dst[cb + (size_t)((nf0 + 1) * 2 + 0) * 32 + lane] = make_uint2(h10, h11);
    dst[cb + (size_t)((nf0 + 1) * 2 + 1) * 32 + lane] = make_uint2(l10, l11);
}

// ---------------------------------------------------------------------------
// conv_A: fp32 [M,K] row-major -> A-frags hi, layout [band64][ks][mf4][32]
// ---------------------------------------------------------------------------
__global__ void conv_A(const float* __restrict__ src, int lda, int Ksteps,
                       uint4* __restrict__ dst) {
    int wg   = blockIdx.x * 8 + (threadIdx.x >> 5);
    int lane = threadIdx.x & 31;
    int ks    = wg % Ksteps;
    int row16 = wg / Ksteps;
    int band64 = row16 >> 2, mf4 = row16 & 3;
    int g = lane >> 2, tc = (lane & 3) * 2;

    const float* p = src + (size_t)(row16 * 16 + g) * lda + ks * 16 + tc;
    float2 p00 = *(const float2*)p;
    float2 p01 = *(const float2*)(p + 8);
    float2 p10 = *(const float2*)(p + (size_t)8 * lda);
    float2 p11 = *(const float2*)(p + (size_t)8 * lda + 8);

    uint4 hi;
    hi.x = hpack(p00.x, p00.y);
    hi.y = hpack(p10.x, p10.y);
    hi.z = hpack(p01.x, p01.y);
    hi.w = hpack(p11.x, p11.y);

    dst[(((size_t)band64 * Ksteps + ks) * 4 + mf4) * 32 + lane] = hi;
}

// ---------------------------------------------------------------------------
// conv_Bd: fp32 [K,N=256] row-major (per slice) -> B-frags hi+lo
// layout [ks][nf32][plane][32]
// ---------------------------------------------------------------------------
__global__ void conv_Bd(const float* __restrict__ srcbase, int ldb, int Ksteps,
                        size_t src_slice_stride,
                        uint2* __restrict__ dstbase, size_t dst_slice_stride) {
    int s = blockIdx.y;
    const float* src = srcbase + (size_t)s * src_slice_stride;
    uint2* dst = dstbase + (size_t)s * dst_slice_stride;

    int wg   = blockIdx.x * 8 + (threadIdx.x >> 5);
    int lane = threadIdx.x & 31;
    int nf   = wg & 15;
    int ks   = (wg >> 4) % Ksteps;
    int band = wg / (16 * Ksteps);
    int g = lane >> 2, tc = (lane & 3) * 2;

    int nfg = band * 16 + nf;
    int n = nfg * 8 + g;
    const float* p = src + (size_t)(ks * 16 + tc) * ldb + n;
    float v0 = p[0];
    float v1 = p[(size_t)ldb];
    float v2 = p[(size_t)8 * ldb];
    float v3 = p[(size_t)9 * ldb];

    unsigned h0, l0, h1, l1;
    hpack2(v0, v1, h0, l0);
    hpack2(v2, v3, h1, l1);

    size_t base = (((size_t)ks * 32 + nfg) * 2) * 32 + lane;
    dst[base]      = make_uint2(h0, h1);
    dst[base + 32] = make_uint2(l0, l1);
}

// ---------------------------------------------------------------------------
// 64(M)x256(N) CTA tile GEMM core, 256 thr (8 warps 2x4, warp tile 32x64),
// prepacked A (hi, 128 uint4/kstep) + B (hi/lo, 1024 uint4/kstep),
// 3-stage cp.async pipeline. acc[2][8][4].
// ---------------------------------------------------------------------------
__device__ __forceinline__ void gemm64x256(const uint4* __restrict__ Ach,
                                           const uint4* __restrict__ Bch,
                                           int Ksteps, float acc[2][8][4]) {
    __shared__ uint4 sA[3][128];
    __shared__ uint4 sB[3][1024];
    int tid = threadIdx.x, wid = tid >> 5, lane = tid & 31;
    int wm = wid >> 2, wn = wid & 3;

    auto issue = [&](int ks) {
        int st = ks % 3;
        const uint4* A = Ach + (size_t)ks * 128;
        const uint4* B = Bch + (size_t)ks * 1024;
        if (tid < 128) cp16(&sA[st][tid], A + tid);
        #pragma unroll
        for (int q = 0; q < 4; q++) cp16(&sB[st][tid + q * 256], B + tid + q * 256);
        cp_commit();
    };
    issue(0);
    issue(1);

    for (int ks = 0; ks < Ksteps; ks++) {
        if (ks + 1 < Ksteps) cp_wait1(); else cp_wait0();
        __syncthreads();
        if (ks + 2 < Ksteps) issue(ks + 2);
        const uint4* sa  = &sA[ks % 3][0];
        const uint2* sbp = (const uint2*)&sB[ks % 3][0];
        uint4 a0 = sa[(wm * 2 + 0) * 32 + lane];
        uint4 a1 = sa[(wm * 2 + 1) * 32 + lane];
        #pragma unroll
        for (int j = 0; j < 8; j++) {
            int nf = wn * 8 + j;
            uint2 bh = sbp[(nf * 2 + 0) * 32 + lane];
            uint2 bl = sbp[(nf * 2 + 1) * 32 + lane];
            mma_f16(acc[0][j], a0, bh); mma_f16(acc[0][j], a0, bl);
            mma_f16(acc[1][j], a1, bh); mma_f16(acc[1][j], a1, bl);
        }
    }
}

// ---------------------------------------------------------------------------
// qkv GEMM: 24 bands of 64 rows x full t=256. Epilogue per band type:
//   q (0..7):  +temb, write fp16 [d][t]
//   k (8..15): +temb, in-CTA softmax over t, write packed B-frags (ctx)
//   v (16..23):+temb, write packed A-frags (ctx)
// ---------------------------------------------------------------------------
__global__ __launch_bounds__(256, 2)
void k_qkv_mma(const uint4* __restrict__ Ap, const uint4* __restrict__ Bx) {
    __shared__ float red[4][64];
    int s = blockIdx.z, band = blockIdx.y;
    const uint4* Ach = Ap + (size_t)band * 16 * 128;
    const uint4* Bch = Bx + (size_t)s * BX_SLICE4;

    float acc[2][8][4] = {};
    gemm64x256(Ach, Bch, 16, acc);

    int tid = threadIdx.x, wid = tid >> 5, lane = tid & 31;
    int wm = wid >> 2, wn = wid & 3;
    int g = lane >> 2, tc = (lane & 3) * 2;

    // temb add (rows d = band*64 + wm*32 + i*16 + hh*8 + g)
    const float* te = g_temb + (size_t)s * OC3 + band * 64;
    float tv[2][2];
    #pragma unroll
    for (int i = 0; i < 2; i++) {
        tv[i][0] = te[wm * 32 + i * 16 + g];
        tv[i][1] = te[wm * 32 + i * 16 + 8 + g];
    }
    #pragma unroll
    for (int i = 0; i < 2; i++)
        #pragma unroll
        for (int j = 0; j < 8; j++) {
            acc[i][j][0] += tv[i][0]; acc[i][j][1] += tv[i][0];
            acc[i][j][2] += tv[i][1]; acc[i][j][3] += tv[i][1];
        }

    if (band < 8) {
        // ---- q: fp16 plain store ----
        __half* gq = g_q16 + (size_t)s * HID * T_;
        #pragma unroll
        for (int i = 0; i < 2; i++) {
            int d = band * 64 + wm * 32 + i * 16 + g;
            #pragma unroll
            for (int j = 0; j < 8; j++) {
                int t = wn * 64 + j * 8 + tc;
                *(__half2*)(gq + (size_t)d * T_ + t) =
                    __floats2half2_rn(acc[i][j][0], acc[i][j][1]);
                *(__half2*)(gq + (size_t)(d + 8) * T_ + t) =
                    __floats2half2_rn(acc[i][j][2], acc[i][j][3]);
            }
        }
    } else if (band < 16) {
        // ---- k: softmax over t (full row in CTA), write ctx B-frags ----
        int kb = band - 8, h = kb >> 1, half = kb & 1;
        // per-thread max for rows (i, hh)
        float mx[2][2];
        #pragma unroll
        for (int i = 0; i < 2; i++) { mx[i][0] = -1e30f; mx[i][1] = -1e30f; }
        #pragma unroll
        for (int i = 0; i < 2; i++)
            #pragma unroll
            for (int j = 0; j < 8; j++) {
                mx[i][0] = fmaxf(mx[i][0], fmaxf(acc[i][j][0], acc[i][j][1]));
                mx[i][1] = fmaxf(mx[i][1], fmaxf(acc[i][j][2], acc[i][j][3]));
            }
        #pragma unroll
        for (int i = 0; i < 2; i++)
            #pragma unroll
            for (int hh = 0; hh < 2; hh++) {
                mx[i][hh] = fmaxf(mx[i][hh], __shfl_xor_sync(0xffffffffu, mx[i][hh], 1));
                mx[i][hh] = fmaxf(mx[i][hh], __shfl_xor_sync(0xffffffffu, mx[i][hh], 2));
            }
        if ((lane & 3) == 0) {
            #pragma unroll
            for (int i = 0; i < 2; i++) {
                red[wn][wm * 32 + i * 16 + g]     = mx[i][0];
                red[wn][wm * 32 + i * 16 + 8 + g] = mx[i][1];
            }
        }
        __syncthreads();
        float MX[2][2];
        #pragma unroll
        for (int i = 0; i < 2; i++)
            #pragma unroll
            for (int hh = 0; hh < 2; hh++) {
                int r = wm * 32 + i * 16 + hh * 8 + g;
                MX[i][hh] = fmaxf(fmaxf(red[0][r], red[1][r]), fmaxf(red[2][r], red[3][r]));
            }
        __syncthreads();
        // exp in place + partial sums
        float sm[2][2] = {};
        #pragma unroll
        for (int i = 0; i < 2; i++)
            #pragma unroll
            for (int j = 0; j < 8; j++) {
                acc[i][j][0] = __expf(acc[i][j][0] - MX[i][0]);
                acc[i][j][1] = __expf(acc[i][j][1] - MX[i][0]);
                acc[i][j][2] = __expf(acc[i][j][2] - MX[i][1]);
                acc[i][j][3] = __expf(acc[i][j][3] - MX[i][1]);
                sm[i][0] += acc[i][j][0] + acc[i][j][1];
                sm[i][1] += acc[i][j][2] + acc[i][j][3];
            }
        #pragma unroll
        for (int i = 0; i < 2; i++)
            #pragma unroll
            for (int hh = 0; hh < 2; hh++) {
                sm[i][hh] += __shfl_xor_sync(0xffffffffu, sm[i][hh], 1);
                sm[i][hh] += __shfl_xor_sync(0xffffffffu, sm[i][hh], 2);
            }
        if ((lane & 3) == 0) {
            #pragma unroll
            for (int i = 0; i < 2; i++) {
                red[wn][wm * 32 + i * 16 + g]     = sm[i][0];
                red[wn][wm * 32 + i * 16 + 8 + g] = sm[i][1];
            }
        }
        __syncthreads();
        float INV[2][2];
        #pragma unroll
        for (int i = 0; i < 2; i++)
            #pragma unroll
            for (int hh = 0; hh < 2; hh++) {
                int r = wm * 32 + i * 16 + hh * 8 + g;
                INV[i][hh] = 1.f / (red[0][r] + red[1][r] + red[2][r] + red[3][r]);
            }
        // pack into ctx B-frags
        uint2* dst = g_kp + ((size_t)s * HEADS + h) * 16384;
        #pragma unroll
        for (int i = 0; i < 2; i++) {
            int nf0 = half * 8 + wm * 4 + i * 2;
            #pragma unroll
            for (int jp = 0; jp < 4; jp++) {
                int ks = wn * 4 + jp;
                float e0[4] = { acc[i][2*jp][0] * INV[i][0], acc[i][2*jp][1] * INV[i][0],
                                acc[i][2*jp][2] * INV[i][1], acc[i][2*jp][3] * INV[i][1] };
                float e1[4] = { acc[i][2*jp+1][0] * INV[i][0], acc[i][2*jp+1][1] * INV[i][0],
                                acc[i][2*jp+1][2] * INV[i][1], acc[i][2*jp+1][3] * INV[i][1] };
                store_hfrag(dst, (size_t)ks * 1024, nf0, lane, e0, e1);
            }
        }
    } else {
        // ---- v: packed A-frags for ctx ----
        int vb = band - 16, h = vb >> 1, half = vb & 1;
        uint4* dst = g_vp + ((size_t)s * HEADS + h) * 4096;
        #pragma unroll
        for (int i = 0; i < 2; i++) {
            int mf = half * 4 + wm * 2 + i;
            #pragma unroll
            for (int jp = 0; jp < 4; jp++) {
                int ks = wn * 4 + jp;
                uint4 hi;
                hi.x = hpack(acc[i][2*jp][0],   acc[i][2*jp][1]);
                hi.y = hpack(acc[i][2*jp][2],   acc[i][2*jp][3]);
                hi.z = hpack(acc[i][2*jp+1][0], acc[i][2*jp+1][1]);
                hi.w = hpack(acc[i][2*jp+1][2], acc[i][2*jp+1][3]);
                dst[(size_t)ks * 256 + mf * 32 + lane] = hi;
            }
        }
    }
}

// ---------------------------------------------------------------------------
// out GEMM: same core, Ksteps=32, epilogue bias + fp32 out
// ---------------------------------------------------------------------------
__global__ __launch_bounds__(256, 2)
void k_out_mma(const uint4* __restrict__ Ap, const uint4* __restrict__ Bp,
               const float* __restrict__ bias, float* __restrict__ out) {
    int s = blockIdx.z, band = blockIdx.y;
    const uint4* Ach = Ap + (size_t)band * 32 * 128;
    const uint4* Bch = Bp + (size_t)s * BATT_SLICE4;

    float acc[2][8][4] = {};
    gemm64x256(Ach, Bch, 32, acc);

    int tid = threadIdx.x, wid = tid >> 5, lane = tid & 31;
    int wm = wid >> 2, wn = wid & 3;
    int g = lane >> 2, tc = (lane & 3) * 2;
    float* Co = out + (size_t)s * 256 * T_;

    #pragma unroll
    for (int i = 0; i < 2; i++) {
        int m = band * 64 + wm * 32 + i * 16 + g;
        float b0 = bias[m], b1 = bias[m + 8];
        #pragma unroll
        for (int j = 0; j < 8; j++) {
            int n = wn * 64 + j * 8 + tc;
            *(float2*)(Co + (size_t)m * T_ + n) =
                make_float2(acc[i][j][0] + b0, acc[i][j][1] + b0);
            *(float2*)(Co + (size_t)(m + 8) * T_ + n) =
                make_float2(acc[i][j][2] + b1, acc[i][j][3] + b1);
        }
    }
}

// ---------------------------------------------------------------------------
// 128x128 prepacked mma core (8 warps 2x4, warp tile 64x32), 3-stage cp.async
// A 256 uint4/kstep, B 512 uint4/kstep. acc[4][4][4]
// ---------------------------------------------------------------------------
__device__ __forceinline__ void frag_mma2(const uint4* sa, const uint2* sbp,
                                          int wm, int wn, int lane, float acc[4][4][4]) {
    uint4 a[4]; uint2 b[4][2];
    #pragma unroll
    for (int i = 0; i < 4; i++) a[i] = sa[(wm * 4 + i) * 32 + lane];
    #pragma unroll
    for (int j = 0; j < 4; j++) {
        int nf = wn * 4 + j;
        b[j][0] = sbp[(nf * 2 + 0) * 32 + lane];
        b[j][1] = sbp[(nf * 2 + 1) * 32 + lane];
    }
    #pragma unroll
    for (int i = 0; i < 4; i++)
        #pragma unroll
        for (int j = 0; j < 4; j++) {
            mma_f16(acc[i][j], a[i], b[j][0]);
            mma_f16(acc[i][j], a[i], b[j][1]);
        }
}

__device__ __forceinline__ void mma_tile3(const uint4* __restrict__ Ach,
                                          const uint4* __restrict__ Bch,
                                          int Ksteps, float acc[4][4][4]) {
    __shared__ uint4 sA[3][256];
    __shared__ uint4 sB[3][512];
    int tid = threadIdx.x, wid = tid >> 5, lane = tid & 31;
    int wm = wid >> 2, wn = wid & 3;

    auto issue = [&](int ks) {
        int st = ks % 3;
        const uint4* A = Ach + (size_t)ks * 256;
        const uint4* B = Bch + (size_t)ks * 512;
        cp16(&sA[st][tid], A + tid);
        cp16(&sB[st][tid], B + tid); cp16(&sB[st][tid + 256], B + tid + 256);
        cp_commit();
    };
    issue(0);
    issue(1);

    for (int ks = 0; ks < Ksteps; ks++) {
        if (ks + 1 < Ksteps) cp_wait1(); else cp_wait0();
        __syncthreads();
        if (ks + 2 < Ksteps) issue(ks + 2);
        frag_mma2(&sA[ks % 3][0], (const uint2*)&sB[ks % 3][0], wm, wn, lane, acc);
    }
}

// ---------------------------------------------------------------------------
// ctx: ctxT[e][d] = sum_t v[e,t]*softmax(k)[d,t] — both operands prepacked
// epilogue -> g_ctxp packed B-frags
// ---------------------------------------------------------------------------
__global__ __launch_bounds__(256, 2)
void k_ctx_mma() {
    int sb = blockIdx.x;
    const uint4* Vch = g_vp + (size_t)sb * 4096;
    const uint4* Kch = (const uint4*)(g_kp + (size_t)sb * 16384);

    float acc[4][4][4] = {};
    mma_tile3(Vch, Kch, 16, acc);

    int tid = threadIdx.x, wid = tid >> 5, lane = tid & 31;
    int wm = wid >> 2, wn = wid & 3;

    uint2* dst = g_ctxp + (size_t)sb * 8192;
    #pragma unroll
    for (int i = 0; i < 4; i++) {
        int nf0 = wm * 8 + 2 * i;
        #pragma unroll
        for (int jp = 0; jp < 2; jp++) {
            int ks = wn * 2 + jp;
            store_hfrag(dst, (size_t)ks * 1024, nf0, lane, acc[i][2 * jp], acc[i][2 * jp + 1]);
        }
    }
}

// ---------------------------------------------------------------------------
// applyT: attT[t][e] = sum_d q[d,t]*ctxT[e,d]
// A = q^T staged from fp16; B = prepacked ctx frags (cp.async)
// epilogue -> gB_att packed B-frags [ks32][nf32][plane][32]
// ---------------------------------------------------------------------------
__global__ __launch_bounds__(256, 2)
void k_applyT_mma() {
    __shared__ uint4 sA[2][256];
    __shared__ uint4 sB[2][512];
    int sb = blockIdx.z, s = sb >> 2, h = sb & 3;
    int mband = blockIdx.x;
    int tid = threadIdx.x, wid = tid >> 5, lane = tid & 31;
    int wm = wid >> 2, wn = wid & 3, g = lane >> 2, tc = (lane & 3) * 2;

    const __half* q = g_q16 + (size_t)s * HID * T_ + (size_t)(h * C_) * T_;
    const uint4* Bch = (const uint4*)(g_ctxp + (size_t)sb * 8192);
    int m = mband * 128 + wid * 16 + g;

    __half av[8];
    auto gloadA = [&](int ks) {
        int k0 = ks * 16 + tc;
        av[0] = q[(size_t)(k0 + 0) * T_ + m];     av[1] = q[(size_t)(k0 + 1) * T_ + m];
        av[2] = q[(size_t)(k0 + 0) * T_ + m + 8]; av[3] = q[(size_t)(k0 + 1) * T_ + m + 8];
        av[4] = q[(size_t)(k0 + 8) * T_ + m];     av[5] = q[(size_t)(k0 + 9) * T_ + m];
        av[6] = q[(size_t)(k0 + 8) * T_ + m + 8]; av[7] = q[(size_t)(k0 + 9) * T_ + m + 8];
    };
    auto sstoreA = [&](int buf) {
        uint4 hi;
        hi.x = hpack_hh(av[0], av[1]);
        hi.y = hpack_hh(av[2], av[3]);
        hi.z = hpack_hh(av[4], av[5]);
        hi.w = hpack_hh(av[6], av[7]);
        sA[buf][wid * 32 + lane] = hi;
    };

    cp16(&sB[0][tid], Bch + tid); cp16(&sB[0][tid + 256], Bch + tid + 256); cp_commit();
    gloadA(0); sstoreA(0);
    cp_wait0();
    __syncthreads();

    float acc[4][4][4] = {};
    for (int ks = 0; ks < 8; ks++) {
        int cur = ks & 1, nxt = cur ^ 1;
        bool more = ks + 1 < 8;
        if (more) {
            const uint4* B = Bch + (size_t)(ks + 1) * 512;
            cp16(&sB[nxt][tid], B + tid); cp16(&sB[nxt][tid + 256], B + tid + 256); cp_commit();
            gloadA(ks + 1);
        }
        frag_mma2(&sA[cur][0], (const uint2*)&sB[cur][0], wm, wn, lane, acc);
        if (more) { sstoreA(nxt); cp_wait0(); __syncthreads(); }
    }

    uint2* dst = gB_att + (size_t)s * BATT_SLICE2;
    #pragma unroll
    for (int i = 0; i < 4; i++) {
        int nf0 = mband * 16 + wm * 8 + 2 * i;
        #pragma unroll
        for (int jp = 0; jp < 2; jp++) {
            int ks = h * 8 + wn * 2 + jp;
            store_hfrag(dst, (size_t)ks * 2048, nf0, lane, acc[i][2 * jp], acc[i][2 * jp + 1]);
        }
    }
}

// ---------------------------------------------------------------------------
// temb
// ---------------------------------------------------------------------------
__global__ void k_temb(const float* __restrict__ time_in,
                       const float* __restrict__ w_time,
                       const float* __restrict__ b_time) {
    int s = blockIdx.x;
    int t = threadIdx.x;
    __shared__ float m[256];
    float v = time_in[(size_t)s * 256 + t];
    float sp = (v > 20.f) ? v : log1pf(__expf(v));
    m[t] = v * tanhf(sp);
    __syncthreads();

    int warp = t >> 5, lane = t & 31;
    for (int o = warp; o < OC3; o += 8) {
        const float* w = w_time + (size_t)o * 256;
        float acc = 0.f;
        #pragma unroll 4
        for (int e = lane; e < 256; e += 32) acc += m[e] * w[e];
        #pragma unroll
        for (int off = 16; off; off >>= 1) acc += __shfl_down_sync(0xffffffffu, acc, off);
        if (lane == 0) g_temb[(size_t)s * OC3 + o] = acc + b_time[o];
    }
}

// ---------------------------------------------------------------------------
extern "C" void kernel_launch(void* const* d_in, const int* in_sizes, int n_in,
                              void* d_out, int out_size) {
    (void)in_sizes; (void)n_in; (void)out_size;
    const float* x       = (const float*)d_in[0];
    const float* time_in = (const float*)d_in[1];
    const float* w_qkv   = (const float*)d_in[2];
    const float* w_time  = (const float*)d_in[3];
    const float* b_time  = (const float*)d_in[4];
    const float* w_out   = (const float*)d_in[5];
    const float* b_out   = (const float*)d_in[6];
    float* out = (float*)d_out;

    uint4* pA_qkv; cudaGetSymbolAddress((void**)&pA_qkv, gA_qkv);
    uint4* pA_out; cudaGetSymbolAddress((void**)&pA_out, gA_out);
    uint2* pB_x;   cudaGetSymbolAddress((void**)&pB_x,   gB_x);
    uint2* pB_att; cudaGetSymbolAddress((void**)&pB_att, gB_att);

    k_temb<<<S_, 256>>>(time_in, w_time, b_time);

    conv_A<<<192, 256>>>(w_qkv, F_, 16, pA_qkv);      // 96 row16-bands x 16 ks
    conv_A<<<64, 256>>>(w_out, HID, 32, pA_out);      // 16 row16-bands x 32 ks
    conv_Bd<<<dim3(64, S_), 256>>>(x, T_, 16, (size_t)F_ * T_, pB_x, (size_t)16 * 2048);

    k_qkv_mma<<<dim3(1, 24, S_), 256>>>(pA_qkv, (const uint4*)pB_x);

    k_ctx_mma<<<S_ * HEADS, 256>>>();
    k_applyT_mma<<<dim3(2, 1, S_ * HEADS), 256>>>();

    k_out_mma<<<dim3(1, 4, S_), 256>>>(pA_out, (const uint4*)pB_att, b_out, out);
}